// round 5
// baseline (speedup 1.0000x reference)
#include <cuda_runtime.h>
#include <math.h>
#include <stdint.h>

#define DD   1024
#define HH   16
#define DHH  64
#define BB   4
#define LL   512
#define TT   2048
#define EE   8
#define KKE  2
#define DFFN 4096
#define NL   (BB*LL)
#define NT   (BB*TT)
#define BHN  (BB*HH)
#define LN_EPS 1e-5f

// ---------------- scratch ----------------
__device__ float g_lnq[(size_t)NL*DD];
__device__ float g_lnt[(size_t)NT*DD];
__device__ float g_qkv[(size_t)NL*3*DD];
__device__ float g_q2 [(size_t)NL*DD];
__device__ float g_kv [(size_t)NT*2*DD];
__device__ float g_attn[(size_t)NL*DD];
__device__ float g_x1 [(size_t)NL*DD];
__device__ float g_x2 [(size_t)NL*DD];
__device__ float g_h1 [(size_t)NL*KKE*DFFN];
__device__ float g_eo [(size_t)NL*KKE*DD];
__device__ int   g_idx [NL*KKE];
__device__ float g_gate[NL*KKE];
__device__ int   g_cnt[EE];
__device__ int   g_off[EE];
__device__ int   g_cur[EE];
__device__ int   g_rowlist[NL*KKE];
__device__ int   g_pairslot[NL*KKE];

// ---------------- helpers ----------------
__device__ __forceinline__ float blk_sum(float v) {
    __shared__ float sh[32];
    int lane = threadIdx.x & 31, w = threadIdx.x >> 5;
    #pragma unroll
    for (int o = 16; o; o >>= 1) v += __shfl_xor_sync(0xffffffffu, v, o);
    if (lane == 0) sh[w] = v;
    __syncthreads();
    if (w == 0) {
        float x = (lane < (int)(blockDim.x >> 5)) ? sh[lane] : 0.f;
        #pragma unroll
        for (int o = 16; o; o >>= 1) x += __shfl_xor_sync(0xffffffffu, x, o);
        if (lane == 0) sh[0] = x;
    }
    __syncthreads();
    float r = sh[0];
    __syncthreads();
    return r;
}

__device__ __forceinline__ float gelu_exact(float x) {
    return 0.5f * x * (1.f + erff(x * 0.70710678118654752f));
}

// ---------------- tf32 mma primitives ----------------
// Unbiased round-to-nearest tf32 conversion (REQUIRED: truncation fails 1e-3).
__device__ __forceinline__ uint32_t f2tf(float f) {
    uint32_t u;
    asm("cvt.rna.tf32.f32 %0, %1;" : "=r"(u) : "f"(f));
    return u;
}

__device__ __forceinline__ void mma8(float* cr, const uint32_t* a, const uint32_t* b) {
    asm volatile(
        "mma.sync.aligned.m16n8k8.row.col.f32.tf32.tf32.f32 "
        "{%0,%1,%2,%3}, {%4,%5,%6,%7}, {%8,%9}, {%0,%1,%2,%3};"
        : "+f"(cr[0]), "+f"(cr[1]), "+f"(cr[2]), "+f"(cr[3])
        : "r"(a[0]), "r"(a[1]), "r"(a[2]), "r"(a[3]), "r"(b[0]), "r"(b[1]));
}

__device__ __forceinline__ void cp16(uint32_t dst, const void* src) {
    asm volatile("cp.async.cg.shared.global [%0], [%1], 16;" :: "r"(dst), "l"(src));
}
__device__ __forceinline__ void cp16p(uint32_t dst, const void* src, bool valid) {
    int sz = valid ? 16 : 0;
    asm volatile("cp.async.cg.shared.global [%0], [%1], 16, %2;" :: "r"(dst), "l"(src), "r"(sz));
}
__device__ __forceinline__ void cpcommit() { asm volatile("cp.async.commit_group;"); }
__device__ __forceinline__ void cpwait1() { asm volatile("cp.async.wait_group 1;"); }
__device__ __forceinline__ void cpwait0() { asm volatile("cp.async.wait_group 0;"); }

// one 32-k slab. A layout [m][AST] k-major.
// BKN=false: B [n][BST] k-major.  BKN=true: B [k][BST] n-major.
template<int WM, int WN, bool BKN, int AST, int BST>
__device__ __forceinline__ void mma_tile(const float* __restrict__ Ab,
                                         const float* __restrict__ Bb,
                                         int wm, int wn, int g, int c,
                                         float (&acc)[WM][WN][4]) {
    #pragma unroll
    for (int kk = 0; kk < 4; kk++) {
        const int k0 = kk * 8;
        uint32_t af[WM][4];
        #pragma unroll
        for (int mi = 0; mi < WM; mi++) {
            const float* Ar = Ab + (wm + mi * 16 + g) * AST + k0 + c;
            af[mi][0] = f2tf(Ar[0]);
            af[mi][1] = f2tf(Ar[8 * AST]);
            af[mi][2] = f2tf(Ar[4]);
            af[mi][3] = f2tf(Ar[8 * AST + 4]);
        }
        uint32_t bf[WN][2];
        #pragma unroll
        for (int ni = 0; ni < WN; ni++) {
            if (BKN) {
                const float* Br = Bb + (k0 + c) * BST + wn + ni * 8 + g;
                bf[ni][0] = f2tf(Br[0]);
                bf[ni][1] = f2tf(Br[4 * BST]);
            } else {
                const float* Br = Bb + (wn + ni * 8 + g) * BST + k0 + c;
                bf[ni][0] = f2tf(Br[0]);
                bf[ni][1] = f2tf(Br[4]);
            }
        }
        #pragma unroll
        for (int mi = 0; mi < WM; mi++)
            #pragma unroll
            for (int ni = 0; ni < WN; ni++)
                mma8(acc[mi][ni], af[mi], bf[ni]);
    }
}

// GEMM tiles: BM=128, BN=64, BK=32
#define TILE_A (128*36)
#define TILE_B (64*36)
#define GEMM_SMEM ((2*TILE_A + 2*TILE_B)*4)   /* 55296 B */

// ---------------- layernorm ----------------
__global__ void __launch_bounds__(256) ln_kernel(const float* __restrict__ x,
                                                 const float* __restrict__ g,
                                                 const float* __restrict__ b,
                                                 float* __restrict__ y) {
    size_t row = blockIdx.x;
    const float* xr = x + row * DD;
    float* yr = y + row * DD;
    int t = threadIdx.x;
    float v[4];
    float s = 0.f;
    #pragma unroll
    for (int i = 0; i < 4; i++) { v[i] = xr[t + 256 * i]; s += v[i]; }
    s = blk_sum(s);
    float mean = s * (1.f / DD);
    float s2 = 0.f;
    #pragma unroll
    for (int i = 0; i < 4; i++) { float d = v[i] - mean; s2 += d * d; }
    s2 = blk_sum(s2);
    float inv = rsqrtf(s2 * (1.f / DD) + LN_EPS);
    #pragma unroll
    for (int i = 0; i < 4; i++) {
        int cc = t + 256 * i;
        yr[cc] = (v[i] - mean) * inv * g[cc] + b[cc];
    }
}

// ---------------- tf32 GEMM: 128x64 tile ----------------
// warps: 4(m) x 2(n); warp tile 32x32 (WM=2, WN=4)
__global__ void __launch_bounds__(256, 2) gemm_tf32(const float* __restrict__ A, int lda,
                                                    const float* __restrict__ W, int ldw,
                                                    float* __restrict__ C, int ldc,
                                                    const float* __restrict__ bias,
                                                    const float* __restrict__ resid, int ldr,
                                                    int Kd) {
    extern __shared__ float sm[];
    float* As = sm;                 // 2 x 128 x 36
    float* Bs = sm + 2 * TILE_A;    // 2 x 64 x 36
    int t = threadIdx.x;
    int row0 = blockIdx.y * 128, col0 = blockIdx.x * 64;
    int larow = t >> 1, lacol = (t & 1) * 16;
    int lbrow = t >> 2, lbcol = (t & 3) * 8;
    const float* Ag = A + (size_t)(row0 + larow) * lda + lacol;
    const float* Wg = W + (size_t)(col0 + lbrow) * ldw + lbcol;
    uint32_t as0 = (uint32_t)__cvta_generic_to_shared(As) + (larow * 36 + lacol) * 4;
    uint32_t bs0 = (uint32_t)__cvta_generic_to_shared(Bs) + (lbrow * 36 + lbcol) * 4;
    int warp = t >> 5, lane = t & 31, g = lane >> 2, c = lane & 3;
    int wm = (warp >> 1) * 32, wn = (warp & 1) * 32;
    float acc[2][4][4] = {};
    int KT = Kd >> 5;
    #pragma unroll
    for (int i = 0; i < 4; i++) cp16(as0 + i * 16, Ag + i * 4);
    cp16(bs0, Wg); cp16(bs0 + 16, Wg + 4);
    cpcommit();
    for (int kt = 0; kt < KT; kt++) {
        int cb = kt & 1;
        if (kt + 1 < KT) {
            int nb = (kt + 1) & 1;
            const float* a = Ag + (kt + 1) * 32;
            const float* w = Wg + (kt + 1) * 32;
            #pragma unroll
            for (int i = 0; i < 4; i++) cp16(as0 + nb * TILE_A * 4 + i * 16, a + i * 4);
            cp16(bs0 + nb * TILE_B * 4, w); cp16(bs0 + nb * TILE_B * 4 + 16, w + 4);
            cpcommit();
            cpwait1();
        } else cpwait0();
        __syncthreads();
        mma_tile<2, 4, false, 36, 36>(As + cb * TILE_A, Bs + cb * TILE_B, wm, wn, g, c, acc);
        __syncthreads();
    }
    #pragma unroll
    for (int mi = 0; mi < 2; mi++) {
        int r = row0 + wm + mi * 16 + g;
        #pragma unroll
        for (int ni = 0; ni < 4; ni++) {
            int cc = col0 + wn + ni * 8 + c * 2;
            float v0 = acc[mi][ni][0], v1 = acc[mi][ni][1];
            float v2 = acc[mi][ni][2], v3 = acc[mi][ni][3];
            if (bias) { float b0 = bias[cc], b1 = bias[cc + 1]; v0 += b0; v1 += b1; v2 += b0; v3 += b1; }
            if (resid) {
                const float* q0 = resid + (size_t)r * ldr + cc;
                const float* q1 = resid + (size_t)(r + 8) * ldr + cc;
                v0 += q0[0]; v1 += q0[1]; v2 += q1[0]; v3 += q1[1];
            }
            *(float2*)(C + (size_t)r * ldc + cc) = make_float2(v0, v1);
            *(float2*)(C + (size_t)(r + 8) * ldc + cc) = make_float2(v2, v3);
        }
    }
}

// ---------------- fused flash attention (tf32) ----------------
#define FA_N 64
#define FA_QS (128*68)
#define FA_KV (64*68)
#define FA_SMEM ((FA_QS + 4*FA_KV + FA_QS)*4)   /* 139264 B */

__global__ void __launch_bounds__(256) flash_tf32(const float* __restrict__ Q, int ldq,
                                                  const float* __restrict__ Kp, int ldk,
                                                  const float* __restrict__ Vp, int ldv,
                                                  float* __restrict__ O, int Lk, float scale) {
    extern __shared__ float sm[];
    float* Qs = sm;
    float* Ks = Qs + FA_QS;
    float* Vs = Ks + 2 * FA_KV;
    float* Ps = Vs + 2 * FA_KV;
    int bh = blockIdx.y, b = bh >> 4, h = bh & 15;
    int q0 = blockIdx.x * 128;
    int t = threadIdx.x;
    const float* Qg = Q + ((size_t)(b * LL + q0)) * ldq + h * DHH;
    const float* Kg = Kp + ((size_t)b * Lk) * ldk + h * DHH;
    const float* Vg = Vp + ((size_t)b * Lk) * ldv + h * DHH;
    uint32_t qs0 = (uint32_t)__cvta_generic_to_shared(Qs);
    uint32_t ks0 = (uint32_t)__cvta_generic_to_shared(Ks);
    uint32_t vs0 = (uint32_t)__cvta_generic_to_shared(Vs);
    {
        int row = t >> 1, segb = (t & 1) * 8;
        const float* qr = Qg + (size_t)row * ldq;
        #pragma unroll
        for (int j = 0; j < 8; j++)
            cp16(qs0 + (row * 68 + (segb + j) * 4) * 4, qr + (segb + j) * 4);
    }
    int kr = t >> 2, kcb = (t & 3) * 16;
    {
        const float* kg = Kg + (size_t)kr * ldk + kcb;
        const float* vg = Vg + (size_t)kr * ldv + kcb;
        uint32_t kb = ks0 + (kr * 68 + kcb) * 4;
        uint32_t vb = vs0 + (kr * 68 + kcb) * 4;
        #pragma unroll
        for (int j = 0; j < 4; j++) cp16(kb + j * 16, kg + j * 4);
        #pragma unroll
        for (int j = 0; j < 4; j++) cp16(vb + j * 16, vg + j * 4);
    }
    cpcommit();
    int warp = t >> 5, lane = t & 31, g = lane >> 2, c = lane & 3;
    int wr = warp * 16;
    float Oa[1][8][4] = {};
    float m0 = -INFINITY, m1 = -INFINITY, l0 = 0.f, l1 = 0.f;
    int niter = Lk / FA_N;
    for (int it = 0; it < niter; it++) {
        if (it + 1 < niter) {
            int buf = (it + 1) & 1;
            const float* kg = Kg + (size_t)((it + 1) * FA_N + kr) * ldk + kcb;
            const float* vg = Vg + (size_t)((it + 1) * FA_N + kr) * ldv + kcb;
            uint32_t kb = ks0 + (buf * FA_KV + kr * 68 + kcb) * 4;
            uint32_t vb = vs0 + (buf * FA_KV + kr * 68 + kcb) * 4;
            #pragma unroll
            for (int j = 0; j < 4; j++) cp16(kb + j * 16, kg + j * 4);
            #pragma unroll
            for (int j = 0; j < 4; j++) cp16(vb + j * 16, vg + j * 4);
            cpcommit();
            cpwait1();
        } else cpwait0();
        __syncthreads();
        const float* Kb = Ks + (it & 1) * FA_KV;
        const float* Vb = Vs + (it & 1) * FA_KV;
        float S[1][8][4] = {};
        mma_tile<1, 8, false, 68, 68>(Qs, Kb, wr, 0, g, c, S);
        mma_tile<1, 8, false, 68, 68>(Qs + 32, Kb + 32, wr, 0, g, c, S);
        float rm0 = -INFINITY, rm1 = -INFINITY;
        #pragma unroll
        for (int ni = 0; ni < 8; ni++) {
            #pragma unroll
            for (int j = 0; j < 4; j++) S[0][ni][j] *= scale;
            rm0 = fmaxf(rm0, fmaxf(S[0][ni][0], S[0][ni][1]));
            rm1 = fmaxf(rm1, fmaxf(S[0][ni][2], S[0][ni][3]));
        }
        rm0 = fmaxf(rm0, __shfl_xor_sync(0xffffffffu, rm0, 1));
        rm0 = fmaxf(rm0, __shfl_xor_sync(0xffffffffu, rm0, 2));
        rm1 = fmaxf(rm1, __shfl_xor_sync(0xffffffffu, rm1, 1));
        rm1 = fmaxf(rm1, __shfl_xor_sync(0xffffffffu, rm1, 2));
        float mn0 = fmaxf(m0, rm0), mn1 = fmaxf(m1, rm1);
        float a0 = __expf(m0 - mn0), a1 = __expf(m1 - mn1);
        float ps0 = 0.f, ps1 = 0.f;
        #pragma unroll
        for (int ni = 0; ni < 8; ni++) {
            float p0 = __expf(S[0][ni][0] - mn0);
            float p1 = __expf(S[0][ni][1] - mn0);
            float p2 = __expf(S[0][ni][2] - mn1);
            float p3 = __expf(S[0][ni][3] - mn1);
            ps0 += p0 + p1; ps1 += p2 + p3;
            *(float2*)&Ps[(wr + g) * 68 + ni * 8 + 2 * c] = make_float2(p0, p1);
            *(float2*)&Ps[(wr + g + 8) * 68 + ni * 8 + 2 * c] = make_float2(p2, p3);
        }
        ps0 += __shfl_xor_sync(0xffffffffu, ps0, 1);
        ps0 += __shfl_xor_sync(0xffffffffu, ps0, 2);
        ps1 += __shfl_xor_sync(0xffffffffu, ps1, 1);
        ps1 += __shfl_xor_sync(0xffffffffu, ps1, 2);
        l0 = l0 * a0 + ps0;
        l1 = l1 * a1 + ps1;
        m0 = mn0; m1 = mn1;
        #pragma unroll
        for (int ni = 0; ni < 8; ni++) {
            Oa[0][ni][0] *= a0; Oa[0][ni][1] *= a0;
            Oa[0][ni][2] *= a1; Oa[0][ni][3] *= a1;
        }
        __syncwarp();
        mma_tile<1, 8, true, 68, 68>(Ps, Vb, wr, 0, g, c, Oa);
        mma_tile<1, 8, true, 68, 68>(Ps + 32, Vb + 32 * 68, wr, 0, g, c, Oa);
        __syncthreads();
    }
    float i0 = 1.f / l0, i1 = 1.f / l1;
    float* Og = O + ((size_t)(b * LL + q0 + wr)) * DD + h * DHH;
    #pragma unroll
    for (int ni = 0; ni < 8; ni++) {
        int cc = ni * 8 + 2 * c;
        *(float2*)(Og + (size_t)g * DD + cc) = make_float2(Oa[0][ni][0] * i0, Oa[0][ni][1] * i0);
        *(float2*)(Og + (size_t)(g + 8) * DD + cc) = make_float2(Oa[0][ni][2] * i1, Oa[0][ni][3] * i1);
    }
}

// ---------------- MoE routing ----------------
__global__ void moe_zero() {
    if (threadIdx.x < EE) g_cnt[threadIdx.x] = 0;
}

__global__ void __launch_bounds__(256) router_topk(const float* __restrict__ H,
                                                   const float* __restrict__ rw,
                                                   const float* __restrict__ rb) {
    int warp = (blockIdx.x * blockDim.x + threadIdx.x) >> 5;
    int lane = threadIdx.x & 31;
    if (warp >= NL) return;
    const float* h = H + (size_t)warp * DD;
    float logit[EE];
    #pragma unroll
    for (int e = 0; e < EE; e++) {
        const float* w = rw + (size_t)e * DD;
        float s = 0.f;
        for (int d = lane; d < DD; d += 32) s += h[d] * w[d];
        #pragma unroll
        for (int o = 16; o; o >>= 1) s += __shfl_xor_sync(0xffffffffu, s, o);
        logit[e] = s + rb[e];
    }
    if (lane == 0) {
        int i0 = 0; float m0 = logit[0];
        #pragma unroll
        for (int e = 1; e < EE; e++) if (logit[e] > m0) { m0 = logit[e]; i0 = e; }
        int i1 = -1; float m1 = -INFINITY;
        #pragma unroll
        for (int e = 0; e < EE; e++) if (e != i0 && logit[e] > m1) { m1 = logit[e]; i1 = e; }
        float z = expf(m1 - m0);
        float inv = 1.f / (1.f + z);
        g_idx[warp * 2] = i0;  g_idx[warp * 2 + 1] = i1;
        g_gate[warp * 2] = inv; g_gate[warp * 2 + 1] = z * inv;
        atomicAdd(&g_cnt[i0], 1);
        atomicAdd(&g_cnt[i1], 1);
    }
}

__global__ void moe_offsets() {
    if (threadIdx.x == 0) {
        int s = 0;
        for (int e = 0; e < EE; e++) { g_off[e] = s; s += g_cnt[e]; g_cur[e] = 0; }
    }
}

__global__ void __launch_bounds__(256) moe_assign() {
    int n = blockIdx.x * blockDim.x + threadIdx.x;
    if (n >= NL) return;
    #pragma unroll
    for (int k = 0; k < KKE; k++) {
        int e = g_idx[n * 2 + k];
        int pos = atomicAdd(&g_cur[e], 1);
        int slot = g_off[e] + pos;
        g_rowlist[slot] = n;
        g_pairslot[n * 2 + k] = slot;
    }
}

// ---------------- MoE grouped tf32 GEMM (128x64 tile) ----------------
__global__ void __launch_bounds__(256, 2) moe_gemm_tf32(const float* __restrict__ A, int lda, int gather,
                                                        const float* __restrict__ W,
                                                        const float* __restrict__ bias,
                                                        int M, int Kd,
                                                        float* __restrict__ C, int ldc, int act) {
    extern __shared__ float sm[];
    float* As = sm;
    float* Bs = sm + 2 * TILE_A;
    int e = blockIdx.z;
    int count = g_cnt[e];
    int row0 = blockIdx.y * 128;
    if (row0 >= count) return;
    int base = g_off[e];
    const float* We = W + (size_t)e * M * Kd;
    const float* be = bias + (size_t)e * M;
    int col0 = blockIdx.x * 64;
    int t = threadIdx.x;
    int larow = t >> 1, lacol = (t & 1) * 16;
    int lbrow = t >> 2, lbcol = (t & 3) * 8;
    int arow = row0 + larow;
    bool valid = arow < count;
    int src;
    if (gather) src = g_rowlist[base + (valid ? arow : 0)];
    else        src = base + (valid ? arow : 0);
    const float* Ag = A + (size_t)src * lda + lacol;
    const float* Wg = We + (size_t)(col0 + lbrow) * Kd + lbcol;
    uint32_t as0 = (uint32_t)__cvta_generic_to_shared(As) + (larow * 36 + lacol) * 4;
    uint32_t bs0 = (uint32_t)__cvta_generic_to_shared(Bs) + (lbrow * 36 + lbcol) * 4;
    int warp = t >> 5, lane = t & 31, g = lane >> 2, c = lane & 3;
    int wm = (warp >> 1) * 32, wn = (warp & 1) * 32;
    float acc[2][4][4] = {};
    int KT = Kd >> 5;
    #pragma unroll
    for (int i = 0; i < 4; i++) cp16p(as0 + i * 16, Ag + i * 4, valid);
    cp16(bs0, Wg); cp16(bs0 + 16, Wg + 4);
    cpcommit();
    for (int kt = 0; kt < KT; kt++) {
        int cb = kt & 1;
        if (kt + 1 < KT) {
            int nb = (kt + 1) & 1;
            const float* a = Ag + (kt + 1) * 32;
            const float* w = Wg + (kt + 1) * 32;
            #pragma unroll
            for (int i = 0; i < 4; i++) cp16p(as0 + nb * TILE_A * 4 + i * 16, a + i * 4, valid);
            cp16(bs0 + nb * TILE_B * 4, w); cp16(bs0 + nb * TILE_B * 4 + 16, w + 4);
            cpcommit();
            cpwait1();
        } else cpwait0();
        __syncthreads();
        mma_tile<2, 4, false, 36, 36>(As + cb * TILE_A, Bs + cb * TILE_B, wm, wn, g, c, acc);
        __syncthreads();
    }
    #pragma unroll
    for (int mi = 0; mi < 2; mi++) {
        int r = row0 + wm + mi * 16 + g;
        #pragma unroll
        for (int ni = 0; ni < 4; ni++) {
            int cc = col0 + wn + ni * 8 + c * 2;
            float b0 = be[cc], b1 = be[cc + 1];
            if (r < count) {
                float v0 = acc[mi][ni][0] + b0, v1 = acc[mi][ni][1] + b1;
                if (act) { v0 = gelu_exact(v0); v1 = gelu_exact(v1); }
                *(float2*)(C + (size_t)(base + r) * ldc + cc) = make_float2(v0, v1);
            }
            if (r + 8 < count) {
                float v2 = acc[mi][ni][2] + b0, v3 = acc[mi][ni][3] + b1;
                if (act) { v2 = gelu_exact(v2); v3 = gelu_exact(v3); }
                *(float2*)(C + (size_t)(base + r + 8) * ldc + cc) = make_float2(v2, v3);
            }
        }
    }
}

// ---------------- final mix ----------------
__global__ void __launch_bounds__(256) moe_mix(const float* __restrict__ x2,
                                               float* __restrict__ out) {
    int i = blockIdx.x * 256 + threadIdx.x;
    int n = i >> 10;
    int d = i & 1023;
    float v = x2[i];
    int s0 = g_pairslot[n * 2], s1 = g_pairslot[n * 2 + 1];
    v += g_gate[n * 2]     * g_eo[(size_t)s0 * DD + d];
    v += g_gate[n * 2 + 1] * g_eo[(size_t)s1 * DD + d];
    out[i] = v;
}

// ---------------- launch ----------------
extern "C" void kernel_launch(void* const* d_in, const int* in_sizes, int n_in,
                              void* d_out, int out_size) {
    const float* latents    = (const float*)d_in[0];
    const float* tokens     = (const float*)d_in[1];
    const float* sa_ln_g    = (const float*)d_in[2];
    const float* sa_ln_b    = (const float*)d_in[3];
    const float* sa_in_w    = (const float*)d_in[4];
    const float* sa_in_b    = (const float*)d_in[5];
    const float* sa_out_w   = (const float*)d_in[6];
    const float* sa_out_b   = (const float*)d_in[7];
    const float* ca_q_ln_g  = (const float*)d_in[8];
    const float* ca_q_ln_b  = (const float*)d_in[9];
    const float* ca_kv_ln_g = (const float*)d_in[10];
    const float* ca_kv_ln_b = (const float*)d_in[11];
    const float* ca_in_w    = (const float*)d_in[12];
    const float* ca_in_b    = (const float*)d_in[13];
    const float* ca_out_w   = (const float*)d_in[14];
    const float* ca_out_b   = (const float*)d_in[15];
    const float* moe_ln_g   = (const float*)d_in[16];
    const float* moe_ln_b   = (const float*)d_in[17];
    const float* router_w   = (const float*)d_in[18];
    const float* router_b   = (const float*)d_in[19];
    const float* e_fc1_w    = (const float*)d_in[20];
    const float* e_fc1_b    = (const float*)d_in[21];
    const float* e_fc2_w    = (const float*)d_in[22];
    const float* e_fc2_b    = (const float*)d_in[23];
    float* out = (float*)d_out;

    static int s_attr_done = 0;
    if (!s_attr_done) {
        cudaFuncSetAttribute(gemm_tf32, cudaFuncAttributeMaxDynamicSharedMemorySize, GEMM_SMEM);
        cudaFuncSetAttribute(moe_gemm_tf32, cudaFuncAttributeMaxDynamicSharedMemorySize, GEMM_SMEM);
        cudaFuncSetAttribute(flash_tf32, cudaFuncAttributeMaxDynamicSharedMemorySize, FA_SMEM);
        s_attr_done = 1;
    }

    float *p_lnq, *p_lnt, *p_qkv, *p_q2, *p_kv, *p_attn, *p_x1, *p_x2, *p_h1, *p_eo;
    cudaGetSymbolAddress((void**)&p_lnq,  g_lnq);
    cudaGetSymbolAddress((void**)&p_lnt,  g_lnt);
    cudaGetSymbolAddress((void**)&p_qkv,  g_qkv);
    cudaGetSymbolAddress((void**)&p_q2,   g_q2);
    cudaGetSymbolAddress((void**)&p_kv,   g_kv);
    cudaGetSymbolAddress((void**)&p_attn, g_attn);
    cudaGetSymbolAddress((void**)&p_x1,   g_x1);
    cudaGetSymbolAddress((void**)&p_x2,   g_x2);
    cudaGetSymbolAddress((void**)&p_h1,   g_h1);
    cudaGetSymbolAddress((void**)&p_eo,   g_eo);

    const float scale = 0.125f;

    // ===== Self-attention =====
    ln_kernel<<<NL, 256>>>(latents, sa_ln_g, sa_ln_b, p_lnq);
    gemm_tf32<<<dim3(48, 16), 256, GEMM_SMEM>>>(p_lnq, DD, sa_in_w, DD, p_qkv, 3 * DD,
                                                sa_in_b, nullptr, 0, DD);
    flash_tf32<<<dim3(4, BHN), 256, FA_SMEM>>>(p_qkv, 3 * DD, p_qkv + DD, 3 * DD,
                                               p_qkv + 2 * DD, 3 * DD, p_attn, LL, scale);
    gemm_tf32<<<dim3(16, 16), 256, GEMM_SMEM>>>(p_attn, DD, sa_out_w, DD, p_x1, DD,
                                                sa_out_b, latents, DD, DD);

    // ===== Cross-attention =====
    ln_kernel<<<NL, 256>>>(p_x1, ca_q_ln_g, ca_q_ln_b, p_lnq);
    ln_kernel<<<NT, 256>>>(tokens, ca_kv_ln_g, ca_kv_ln_b, p_lnt);
    gemm_tf32<<<dim3(16, 16), 256, GEMM_SMEM>>>(p_lnq, DD, ca_in_w, DD, p_q2, DD,
                                                ca_in_b, nullptr, 0, DD);
    gemm_tf32<<<dim3(32, 64), 256, GEMM_SMEM>>>(p_lnt, DD, ca_in_w + (size_t)DD * DD, DD,
                                                p_kv, 2 * DD, ca_in_b + DD, nullptr, 0, DD);
    flash_tf32<<<dim3(4, BHN), 256, FA_SMEM>>>(p_q2, DD, p_kv, 2 * DD,
                                               p_kv + DD, 2 * DD, p_attn, TT, scale);
    gemm_tf32<<<dim3(16, 16), 256, GEMM_SMEM>>>(p_attn, DD, ca_out_w, DD, p_x2, DD,
                                                ca_out_b, p_x1, DD, DD);

    // ===== MoE =====
    ln_kernel<<<NL, 256>>>(p_x2, moe_ln_g, moe_ln_b, p_lnq);
    moe_zero<<<1, 32>>>();
    router_topk<<<NL / 8, 256>>>(p_lnq, router_w, router_b);
    moe_offsets<<<1, 1>>>();
    moe_assign<<<NL / 256, 256>>>();
    moe_gemm_tf32<<<dim3(DFFN / 64, 16, EE), 256, GEMM_SMEM>>>(p_lnq, DD, 1, e_fc1_w, e_fc1_b,
                                                               DFFN, DD, p_h1, DFFN, 1);
    moe_gemm_tf32<<<dim3(DD / 64, 16, EE), 256, GEMM_SMEM>>>(p_h1, DFFN, 0, e_fc2_w, e_fc2_b,
                                                             DD, DFFN, p_eo, DD, 0);
    moe_mix<<<(NL * DD) / 256, 256>>>(p_x2, out);
}

// round 6
// speedup vs baseline: 1.0847x; 1.0847x over previous
#include <cuda_runtime.h>
#include <math.h>
#include <stdint.h>

#define DD   1024
#define HH   16
#define DHH  64
#define BB   4
#define LL   512
#define TT   2048
#define EE   8
#define KKE  2
#define DFFN 4096
#define NL   (BB*LL)
#define NT   (BB*TT)
#define BHN  (BB*HH)
#define LN_EPS 1e-5f

// ---------------- scratch ----------------
__device__ float g_lnq[(size_t)NL*DD];
__device__ float g_lnt[(size_t)NT*DD];
__device__ float g_qkv[(size_t)NL*3*DD];
__device__ float g_q2 [(size_t)NL*DD];
__device__ float g_kv [(size_t)NT*2*DD];
__device__ float g_attn[(size_t)NL*DD];
__device__ float g_x1 [(size_t)NL*DD];
__device__ float g_x2 [(size_t)NL*DD];
__device__ float g_h1 [(size_t)NL*KKE*DFFN];
__device__ float g_eo [(size_t)NL*KKE*DD];
__device__ int   g_idx [NL*KKE];
__device__ float g_gate[NL*KKE];
__device__ int   g_cnt[EE];
__device__ int   g_off[EE];
__device__ int   g_cur[EE];
__device__ int   g_rowlist[NL*KKE];
__device__ int   g_pairslot[NL*KKE];

// ---------------- helpers ----------------
__device__ __forceinline__ float blk_sum(float v) {
    __shared__ float sh[32];
    int lane = threadIdx.x & 31, w = threadIdx.x >> 5;
    #pragma unroll
    for (int o = 16; o; o >>= 1) v += __shfl_xor_sync(0xffffffffu, v, o);
    if (lane == 0) sh[w] = v;
    __syncthreads();
    if (w == 0) {
        float x = (lane < (int)(blockDim.x >> 5)) ? sh[lane] : 0.f;
        #pragma unroll
        for (int o = 16; o; o >>= 1) x += __shfl_xor_sync(0xffffffffu, x, o);
        if (lane == 0) sh[0] = x;
    }
    __syncthreads();
    float r = sh[0];
    __syncthreads();
    return r;
}

__device__ __forceinline__ float gelu_exact(float x) {
    return 0.5f * x * (1.f + erff(x * 0.70710678118654752f));
}

// ---------------- tf32 mma primitives ----------------
// Unbiased round-to-nearest tf32 (REQUIRED: truncation fails 1e-3).
__device__ __forceinline__ uint32_t f2tf(float f) {
    uint32_t u;
    asm("cvt.rna.tf32.f32 %0, %1;" : "=r"(u) : "f"(f));
    return u;
}

__device__ __forceinline__ void mma8(float* cr, const uint32_t* a, const uint32_t* b) {
    asm volatile(
        "mma.sync.aligned.m16n8k8.row.col.f32.tf32.tf32.f32 "
        "{%0,%1,%2,%3}, {%4,%5,%6,%7}, {%8,%9}, {%0,%1,%2,%3};"
        : "+f"(cr[0]), "+f"(cr[1]), "+f"(cr[2]), "+f"(cr[3])
        : "r"(a[0]), "r"(a[1]), "r"(a[2]), "r"(a[3]), "r"(b[0]), "r"(b[1]));
}

__device__ __forceinline__ void cp16(uint32_t dst, const void* src) {
    asm volatile("cp.async.cg.shared.global [%0], [%1], 16;" :: "r"(dst), "l"(src));
}
__device__ __forceinline__ void cpcommit() { asm volatile("cp.async.commit_group;"); }
__device__ __forceinline__ void cpwait1() { asm volatile("cp.async.wait_group 1;"); }
__device__ __forceinline__ void cpwait0() { asm volatile("cp.async.wait_group 0;"); }

// ============ GEMM engine: 128x128 tile, BK=32, tf32-in-smem, k-pair-permuted ============
// smem layout per tile row (stride 40 u32): within each 8-k group, value k stored
// at (k&3)*2 + (k>>2)  =>  (c, c+4) adjacent -> uint2 fragment loads.
#define AST 40
#define TILEU (128*AST)
#define GEMM_SMEM (4*TILEU*4)   /* 2 bufs x (A+B) x 4B = 81920 */

// store 16 consecutive-k floats (2 groups of 8) cvt'd+permuted. dst = row*AST + kbase.
__device__ __forceinline__ void st16(uint32_t* dst, const float* v) {
    #pragma unroll
    for (int gr = 0; gr < 2; gr++) {
        #pragma unroll
        for (int p = 0; p < 4; p++) {
            uint2 u;
            u.x = f2tf(v[gr * 8 + p]);
            u.y = f2tf(v[gr * 8 + p + 4]);
            *(uint2*)(dst + gr * 8 + p * 2) = u;
        }
    }
}

// one 32-k slab from tf32 smem. WM=4, WN=4 (warp tile 64x32).
__device__ __forceinline__ void mma_u(const uint32_t* __restrict__ Ab,
                                      const uint32_t* __restrict__ Bb,
                                      int wm, int wn, int g, int c,
                                      float (&acc)[4][4][4]) {
    #pragma unroll
    for (int kk = 0; kk < 4; kk++) {
        const int ko = kk * 8 + 2 * c;
        uint32_t af[4][4];
        #pragma unroll
        for (int mi = 0; mi < 4; mi++) {
            uint2 lo = *(const uint2*)(Ab + (wm + mi * 16 + g) * AST + ko);
            uint2 hi = *(const uint2*)(Ab + (wm + mi * 16 + g + 8) * AST + ko);
            af[mi][0] = lo.x; af[mi][2] = lo.y;
            af[mi][1] = hi.x; af[mi][3] = hi.y;
        }
        uint32_t bf[4][2];
        #pragma unroll
        for (int ni = 0; ni < 4; ni++) {
            uint2 bb = *(const uint2*)(Bb + (wn + ni * 8 + g) * AST + ko);
            bf[ni][0] = bb.x; bf[ni][1] = bb.y;
        }
        #pragma unroll
        for (int mi = 0; mi < 4; mi++)
            #pragma unroll
            for (int ni = 0; ni < 4; ni++)
                mma8(acc[mi][ni], af[mi], bf[ni]);
    }
}

// float-smem slab for flash attention (cvt inline). A [m][AST2] k-major.
// BKN=false: B [n][BST] k-major.  BKN=true: B [k][BST] n-major.
template<int WM, int WN, bool BKN, int AST2, int BST>
__device__ __forceinline__ void mma_tile(const float* __restrict__ Ab,
                                         const float* __restrict__ Bb,
                                         int wm, int wn, int g, int c,
                                         float (&acc)[WM][WN][4]) {
    #pragma unroll
    for (int kk = 0; kk < 4; kk++) {
        const int k0 = kk * 8;
        uint32_t af[WM][4];
        #pragma unroll
        for (int mi = 0; mi < WM; mi++) {
            const float* Ar = Ab + (wm + mi * 16 + g) * AST2 + k0 + c;
            af[mi][0] = f2tf(Ar[0]);
            af[mi][1] = f2tf(Ar[8 * AST2]);
            af[mi][2] = f2tf(Ar[4]);
            af[mi][3] = f2tf(Ar[8 * AST2 + 4]);
        }
        uint32_t bf[WN][2];
        #pragma unroll
        for (int ni = 0; ni < WN; ni++) {
            if (BKN) {
                const float* Br = Bb + (k0 + c) * BST + wn + ni * 8 + g;
                bf[ni][0] = f2tf(Br[0]);
                bf[ni][1] = f2tf(Br[4 * BST]);
            } else {
                const float* Br = Bb + (wn + ni * 8 + g) * BST + k0 + c;
                bf[ni][0] = f2tf(Br[0]);
                bf[ni][1] = f2tf(Br[4]);
            }
        }
        #pragma unroll
        for (int mi = 0; mi < WM; mi++)
            #pragma unroll
            for (int ni = 0; ni < WN; ni++)
                mma8(acc[mi][ni], af[mi], bf[ni]);
    }
}

// ---------------- layernorm ----------------
__global__ void __launch_bounds__(256) ln_kernel(const float* __restrict__ x,
                                                 const float* __restrict__ g,
                                                 const float* __restrict__ b,
                                                 float* __restrict__ y) {
    size_t row = blockIdx.x;
    const float* xr = x + row * DD;
    float* yr = y + row * DD;
    int t = threadIdx.x;
    float v[4];
    float s = 0.f;
    #pragma unroll
    for (int i = 0; i < 4; i++) { v[i] = xr[t + 256 * i]; s += v[i]; }
    s = blk_sum(s);
    float mean = s * (1.f / DD);
    float s2 = 0.f;
    #pragma unroll
    for (int i = 0; i < 4; i++) { float d = v[i] - mean; s2 += d * d; }
    s2 = blk_sum(s2);
    float inv = rsqrtf(s2 * (1.f / DD) + LN_EPS);
    #pragma unroll
    for (int i = 0; i < 4; i++) {
        int cc = t + 256 * i;
        yr[cc] = (v[i] - mean) * inv * g[cc] + b[cc];
    }
}

// ---------------- tf32 GEMM: 128x128 tile, tf32-in-smem ----------------
__global__ void __launch_bounds__(256, 2) gemm_tf32(const float* __restrict__ A, int lda,
                                                    const float* __restrict__ W, int ldw,
                                                    float* __restrict__ C, int ldc,
                                                    const float* __restrict__ bias,
                                                    const float* __restrict__ resid, int ldr,
                                                    int Kd) {
    extern __shared__ uint32_t smu[];
    uint32_t* As = smu;                // 2 x 128 x 40
    uint32_t* Bs = smu + 2 * TILEU;
    int t = threadIdx.x;
    int row0 = blockIdx.y * 128, col0 = blockIdx.x * 128;
    int lrow = t >> 1, kb = (t & 1) * 16;
    const float* Ag = A + (size_t)(row0 + lrow) * lda + kb;
    const float* Wg = W + (size_t)(col0 + lrow) * ldw + kb;
    int soff = lrow * AST + kb;
    int warp = t >> 5, lane = t & 31, g = lane >> 2, c = lane & 3;
    int wm = (warp >> 2) * 64, wn = (warp & 3) * 32;
    float acc[4][4][4] = {};
    int KT = Kd >> 5;
    float a_st[16], b_st[16];
    #pragma unroll
    for (int i = 0; i < 4; i++) *(float4*)(a_st + 4 * i) = *(const float4*)(Ag + 4 * i);
    #pragma unroll
    for (int i = 0; i < 4; i++) *(float4*)(b_st + 4 * i) = *(const float4*)(Wg + 4 * i);
    st16(As + soff, a_st);
    st16(Bs + soff, b_st);
    __syncthreads();
    for (int kt = 0; kt < KT; kt++) {
        int cb = kt & 1;
        if (kt + 1 < KT) {
            const float* a = Ag + (kt + 1) * 32;
            const float* w = Wg + (kt + 1) * 32;
            #pragma unroll
            for (int i = 0; i < 4; i++) *(float4*)(a_st + 4 * i) = *(const float4*)(a + 4 * i);
            #pragma unroll
            for (int i = 0; i < 4; i++) *(float4*)(b_st + 4 * i) = *(const float4*)(w + 4 * i);
        }
        mma_u(As + cb * TILEU, Bs + cb * TILEU, wm, wn, g, c, acc);
        if (kt + 1 < KT) {
            int nb = (kt + 1) & 1;
            st16(As + nb * TILEU + soff, a_st);
            st16(Bs + nb * TILEU + soff, b_st);
            __syncthreads();
        }
    }
    #pragma unroll
    for (int mi = 0; mi < 4; mi++) {
        int r = row0 + wm + mi * 16 + g;
        #pragma unroll
        for (int ni = 0; ni < 4; ni++) {
            int cc = col0 + wn + ni * 8 + c * 2;
            float v0 = acc[mi][ni][0], v1 = acc[mi][ni][1];
            float v2 = acc[mi][ni][2], v3 = acc[mi][ni][3];
            if (bias) { float b0 = bias[cc], b1 = bias[cc + 1]; v0 += b0; v1 += b1; v2 += b0; v3 += b1; }
            if (resid) {
                const float* q0 = resid + (size_t)r * ldr + cc;
                const float* q1 = resid + (size_t)(r + 8) * ldr + cc;
                v0 += q0[0]; v1 += q0[1]; v2 += q1[0]; v3 += q1[1];
            }
            *(float2*)(C + (size_t)r * ldc + cc) = make_float2(v0, v1);
            *(float2*)(C + (size_t)(r + 8) * ldc + cc) = make_float2(v2, v3);
        }
    }
}

// ---------------- fused flash attention (tf32, unchanged engine) ----------------
#define FA_N 64
#define FA_QS (128*68)
#define FA_KV (64*68)
#define FA_SMEM ((FA_QS + 4*FA_KV + FA_QS)*4)

__global__ void __launch_bounds__(256) flash_tf32(const float* __restrict__ Q, int ldq,
                                                  const float* __restrict__ Kp, int ldk,
                                                  const float* __restrict__ Vp, int ldv,
                                                  float* __restrict__ O, int Lk, float scale) {
    extern __shared__ float sm[];
    float* Qs = sm;
    float* Ks = Qs + FA_QS;
    float* Vs = Ks + 2 * FA_KV;
    float* Ps = Vs + 2 * FA_KV;
    int bh = blockIdx.y, b = bh >> 4, h = bh & 15;
    int q0 = blockIdx.x * 128;
    int t = threadIdx.x;
    const float* Qg = Q + ((size_t)(b * LL + q0)) * ldq + h * DHH;
    const float* Kg = Kp + ((size_t)b * Lk) * ldk + h * DHH;
    const float* Vg = Vp + ((size_t)b * Lk) * ldv + h * DHH;
    uint32_t qs0 = (uint32_t)__cvta_generic_to_shared(Qs);
    uint32_t ks0 = (uint32_t)__cvta_generic_to_shared(Ks);
    uint32_t vs0 = (uint32_t)__cvta_generic_to_shared(Vs);
    {
        int row = t >> 1, segb = (t & 1) * 8;
        const float* qr = Qg + (size_t)row * ldq;
        #pragma unroll
        for (int j = 0; j < 8; j++)
            cp16(qs0 + (row * 68 + (segb + j) * 4) * 4, qr + (segb + j) * 4);
    }
    int kr = t >> 2, kcb = (t & 3) * 16;
    {
        const float* kg = Kg + (size_t)kr * ldk + kcb;
        const float* vg = Vg + (size_t)kr * ldv + kcb;
        uint32_t kb = ks0 + (kr * 68 + kcb) * 4;
        uint32_t vb = vs0 + (kr * 68 + kcb) * 4;
        #pragma unroll
        for (int j = 0; j < 4; j++) cp16(kb + j * 16, kg + j * 4);
        #pragma unroll
        for (int j = 0; j < 4; j++) cp16(vb + j * 16, vg + j * 4);
    }
    cpcommit();
    int warp = t >> 5, lane = t & 31, g = lane >> 2, c = lane & 3;
    int wr = warp * 16;
    float Oa[1][8][4] = {};
    float m0 = -INFINITY, m1 = -INFINITY, l0 = 0.f, l1 = 0.f;
    int niter = Lk / FA_N;
    for (int it = 0; it < niter; it++) {
        if (it + 1 < niter) {
            int buf = (it + 1) & 1;
            const float* kg = Kg + (size_t)((it + 1) * FA_N + kr) * ldk + kcb;
            const float* vg = Vg + (size_t)((it + 1) * FA_N + kr) * ldv + kcb;
            uint32_t kb = ks0 + (buf * FA_KV + kr * 68 + kcb) * 4;
            uint32_t vb = vs0 + (buf * FA_KV + kr * 68 + kcb) * 4;
            #pragma unroll
            for (int j = 0; j < 4; j++) cp16(kb + j * 16, kg + j * 4);
            #pragma unroll
            for (int j = 0; j < 4; j++) cp16(vb + j * 16, vg + j * 4);
            cpcommit();
            cpwait1();
        } else cpwait0();
        __syncthreads();
        const float* Kb = Ks + (it & 1) * FA_KV;
        const float* Vb = Vs + (it & 1) * FA_KV;
        float S[1][8][4] = {};
        mma_tile<1, 8, false, 68, 68>(Qs, Kb, wr, 0, g, c, S);
        mma_tile<1, 8, false, 68, 68>(Qs + 32, Kb + 32, wr, 0, g, c, S);
        float rm0 = -INFINITY, rm1 = -INFINITY;
        #pragma unroll
        for (int ni = 0; ni < 8; ni++) {
            #pragma unroll
            for (int j = 0; j < 4; j++) S[0][ni][j] *= scale;
            rm0 = fmaxf(rm0, fmaxf(S[0][ni][0], S[0][ni][1]));
            rm1 = fmaxf(rm1, fmaxf(S[0][ni][2], S[0][ni][3]));
        }
        rm0 = fmaxf(rm0, __shfl_xor_sync(0xffffffffu, rm0, 1));
        rm0 = fmaxf(rm0, __shfl_xor_sync(0xffffffffu, rm0, 2));
        rm1 = fmaxf(rm1, __shfl_xor_sync(0xffffffffu, rm1, 1));
        rm1 = fmaxf(rm1, __shfl_xor_sync(0xffffffffu, rm1, 2));
        float mn0 = fmaxf(m0, rm0), mn1 = fmaxf(m1, rm1);
        float a0 = __expf(m0 - mn0), a1 = __expf(m1 - mn1);
        float ps0 = 0.f, ps1 = 0.f;
        #pragma unroll
        for (int ni = 0; ni < 8; ni++) {
            float p0 = __expf(S[0][ni][0] - mn0);
            float p1 = __expf(S[0][ni][1] - mn0);
            float p2 = __expf(S[0][ni][2] - mn1);
            float p3 = __expf(S[0][ni][3] - mn1);
            ps0 += p0 + p1; ps1 += p2 + p3;
            *(float2*)&Ps[(wr + g) * 68 + ni * 8 + 2 * c] = make_float2(p0, p1);
            *(float2*)&Ps[(wr + g + 8) * 68 + ni * 8 + 2 * c] = make_float2(p2, p3);
        }
        ps0 += __shfl_xor_sync(0xffffffffu, ps0, 1);
        ps0 += __shfl_xor_sync(0xffffffffu, ps0, 2);
        ps1 += __shfl_xor_sync(0xffffffffu, ps1, 1);
        ps1 += __shfl_xor_sync(0xffffffffu, ps1, 2);
        l0 = l0 * a0 + ps0;
        l1 = l1 * a1 + ps1;
        m0 = mn0; m1 = mn1;
        #pragma unroll
        for (int ni = 0; ni < 8; ni++) {
            Oa[0][ni][0] *= a0; Oa[0][ni][1] *= a0;
            Oa[0][ni][2] *= a1; Oa[0][ni][3] *= a1;
        }
        __syncwarp();
        mma_tile<1, 8, true, 68, 68>(Ps, Vb, wr, 0, g, c, Oa);
        mma_tile<1, 8, true, 68, 68>(Ps + 32, Vb + 32 * 68, wr, 0, g, c, Oa);
        __syncthreads();
    }
    float i0 = 1.f / l0, i1 = 1.f / l1;
    float* Og = O + ((size_t)(b * LL + q0 + wr)) * DD + h * DHH;
    #pragma unroll
    for (int ni = 0; ni < 8; ni++) {
        int cc = ni * 8 + 2 * c;
        *(float2*)(Og + (size_t)g * DD + cc) = make_float2(Oa[0][ni][0] * i0, Oa[0][ni][1] * i0);
        *(float2*)(Og + (size_t)(g + 8) * DD + cc) = make_float2(Oa[0][ni][2] * i1, Oa[0][ni][3] * i1);
    }
}

// ---------------- MoE routing ----------------
__global__ void moe_zero() {
    if (threadIdx.x < EE) g_cnt[threadIdx.x] = 0;
}

__global__ void __launch_bounds__(256) router_topk(const float* __restrict__ H,
                                                   const float* __restrict__ rw,
                                                   const float* __restrict__ rb) {
    int warp = (blockIdx.x * blockDim.x + threadIdx.x) >> 5;
    int lane = threadIdx.x & 31;
    if (warp >= NL) return;
    const float* h = H + (size_t)warp * DD;
    float logit[EE];
    #pragma unroll
    for (int e = 0; e < EE; e++) {
        const float* w = rw + (size_t)e * DD;
        float s = 0.f;
        for (int d = lane; d < DD; d += 32) s += h[d] * w[d];
        #pragma unroll
        for (int o = 16; o; o >>= 1) s += __shfl_xor_sync(0xffffffffu, s, o);
        logit[e] = s + rb[e];
    }
    if (lane == 0) {
        int i0 = 0; float m0 = logit[0];
        #pragma unroll
        for (int e = 1; e < EE; e++) if (logit[e] > m0) { m0 = logit[e]; i0 = e; }
        int i1 = -1; float m1 = -INFINITY;
        #pragma unroll
        for (int e = 0; e < EE; e++) if (e != i0 && logit[e] > m1) { m1 = logit[e]; i1 = e; }
        float z = expf(m1 - m0);
        float inv = 1.f / (1.f + z);
        g_idx[warp * 2] = i0;  g_idx[warp * 2 + 1] = i1;
        g_gate[warp * 2] = inv; g_gate[warp * 2 + 1] = z * inv;
        atomicAdd(&g_cnt[i0], 1);
        atomicAdd(&g_cnt[i1], 1);
    }
}

__global__ void moe_offsets() {
    if (threadIdx.x == 0) {
        int s = 0;
        for (int e = 0; e < EE; e++) { g_off[e] = s; s += g_cnt[e]; g_cur[e] = 0; }
    }
}

__global__ void __launch_bounds__(256) moe_assign() {
    int n = blockIdx.x * blockDim.x + threadIdx.x;
    if (n >= NL) return;
    #pragma unroll
    for (int k = 0; k < KKE; k++) {
        int e = g_idx[n * 2 + k];
        int pos = atomicAdd(&g_cur[e], 1);
        int slot = g_off[e] + pos;
        g_rowlist[slot] = n;
        g_pairslot[n * 2 + k] = slot;
    }
}

// ---------------- MoE grouped tf32 GEMM (128x128, tf32-in-smem) ----------------
__global__ void __launch_bounds__(256, 2) moe_gemm_tf32(const float* __restrict__ A, int lda, int gather,
                                                        const float* __restrict__ W,
                                                        const float* __restrict__ bias,
                                                        int M, int Kd,
                                                        float* __restrict__ C, int ldc, int act) {
    extern __shared__ uint32_t smu[];
    uint32_t* As = smu;
    uint32_t* Bs = smu + 2 * TILEU;
    int e = blockIdx.z;
    int count = g_cnt[e];
    int row0 = blockIdx.y * 128;
    if (row0 >= count) return;
    int base = g_off[e];
    const float* We = W + (size_t)e * M * Kd;
    const float* be = bias + (size_t)e * M;
    int col0 = blockIdx.x * 128;
    int t = threadIdx.x;
    int lrow = t >> 1, kb = (t & 1) * 16;
    int arow = row0 + lrow;
    int src;
    if (gather) src = g_rowlist[base + (arow < count ? arow : count - 1)];
    else        src = base + (arow < count ? arow : count - 1);
    const float* Ag = A + (size_t)src * lda + kb;
    const float* Wg = We + (size_t)(col0 + lrow) * Kd + kb;
    int soff = lrow * AST + kb;
    int warp = t >> 5, lane = t & 31, g = lane >> 2, c = lane & 3;
    int wm = (warp >> 2) * 64, wn = (warp & 3) * 32;
    float acc[4][4][4] = {};
    int KT = Kd >> 5;
    float a_st[16], b_st[16];
    #pragma unroll
    for (int i = 0; i < 4; i++) *(float4*)(a_st + 4 * i) = *(const float4*)(Ag + 4 * i);
    #pragma unroll
    for (int i = 0; i < 4; i++) *(float4*)(b_st + 4 * i) = *(const float4*)(Wg + 4 * i);
    st16(As + soff, a_st);
    st16(Bs + soff, b_st);
    __syncthreads();
    for (int kt = 0; kt < KT; kt++) {
        int cb = kt & 1;
        if (kt + 1 < KT) {
            const float* a = Ag + (kt + 1) * 32;
            const float* w = Wg + (kt + 1) * 32;
            #pragma unroll
            for (int i = 0; i < 4; i++) *(float4*)(a_st + 4 * i) = *(const float4*)(a + 4 * i);
            #pragma unroll
            for (int i = 0; i < 4; i++) *(float4*)(b_st + 4 * i) = *(const float4*)(w + 4 * i);
        }
        mma_u(As + cb * TILEU, Bs + cb * TILEU, wm, wn, g, c, acc);
        if (kt + 1 < KT) {
            int nb = (kt + 1) & 1;
            st16(As + nb * TILEU + soff, a_st);
            st16(Bs + nb * TILEU + soff, b_st);
            __syncthreads();
        }
    }
    #pragma unroll
    for (int mi = 0; mi < 4; mi++) {
        int r = row0 + wm + mi * 16 + g;
        #pragma unroll
        for (int ni = 0; ni < 4; ni++) {
            int cc = col0 + wn + ni * 8 + c * 2;
            float b0 = be[cc], b1 = be[cc + 1];
            if (r < count) {
                float v0 = acc[mi][ni][0] + b0, v1 = acc[mi][ni][1] + b1;
                if (act) { v0 = gelu_exact(v0); v1 = gelu_exact(v1); }
                *(float2*)(C + (size_t)(base + r) * ldc + cc) = make_float2(v0, v1);
            }
            if (r + 8 < count) {
                float v2 = acc[mi][ni][2] + b0, v3 = acc[mi][ni][3] + b1;
                if (act) { v2 = gelu_exact(v2); v3 = gelu_exact(v3); }
                *(float2*)(C + (size_t)(base + r + 8) * ldc + cc) = make_float2(v2, v3);
            }
        }
    }
}

// ---------------- final mix ----------------
__global__ void __launch_bounds__(256) moe_mix(const float* __restrict__ x2,
                                               float* __restrict__ out) {
    int i = blockIdx.x * 256 + threadIdx.x;
    int n = i >> 10;
    int d = i & 1023;
    float v = x2[i];
    int s0 = g_pairslot[n * 2], s1 = g_pairslot[n * 2 + 1];
    v += g_gate[n * 2]     * g_eo[(size_t)s0 * DD + d];
    v += g_gate[n * 2 + 1] * g_eo[(size_t)s1 * DD + d];
    out[i] = v;
}

// ---------------- launch ----------------
extern "C" void kernel_launch(void* const* d_in, const int* in_sizes, int n_in,
                              void* d_out, int out_size) {
    const float* latents    = (const float*)d_in[0];
    const float* tokens     = (const float*)d_in[1];
    const float* sa_ln_g    = (const float*)d_in[2];
    const float* sa_ln_b    = (const float*)d_in[3];
    const float* sa_in_w    = (const float*)d_in[4];
    const float* sa_in_b    = (const float*)d_in[5];
    const float* sa_out_w   = (const float*)d_in[6];
    const float* sa_out_b   = (const float*)d_in[7];
    const float* ca_q_ln_g  = (const float*)d_in[8];
    const float* ca_q_ln_b  = (const float*)d_in[9];
    const float* ca_kv_ln_g = (const float*)d_in[10];
    const float* ca_kv_ln_b = (const float*)d_in[11];
    const float* ca_in_w    = (const float*)d_in[12];
    const float* ca_in_b    = (const float*)d_in[13];
    const float* ca_out_w   = (const float*)d_in[14];
    const float* ca_out_b   = (const float*)d_in[15];
    const float* moe_ln_g   = (const float*)d_in[16];
    const float* moe_ln_b   = (const float*)d_in[17];
    const float* router_w   = (const float*)d_in[18];
    const float* router_b   = (const float*)d_in[19];
    const float* e_fc1_w    = (const float*)d_in[20];
    const float* e_fc1_b    = (const float*)d_in[21];
    const float* e_fc2_w    = (const float*)d_in[22];
    const float* e_fc2_b    = (const float*)d_in[23];
    float* out = (float*)d_out;

    static int s_attr_done = 0;
    if (!s_attr_done) {
        cudaFuncSetAttribute(gemm_tf32, cudaFuncAttributeMaxDynamicSharedMemorySize, GEMM_SMEM);
        cudaFuncSetAttribute(moe_gemm_tf32, cudaFuncAttributeMaxDynamicSharedMemorySize, GEMM_SMEM);
        cudaFuncSetAttribute(flash_tf32, cudaFuncAttributeMaxDynamicSharedMemorySize, FA_SMEM);
        s_attr_done = 1;
    }

    float *p_lnq, *p_lnt, *p_qkv, *p_q2, *p_kv, *p_attn, *p_x1, *p_x2, *p_h1, *p_eo;
    cudaGetSymbolAddress((void**)&p_lnq,  g_lnq);
    cudaGetSymbolAddress((void**)&p_lnt,  g_lnt);
    cudaGetSymbolAddress((void**)&p_qkv,  g_qkv);
    cudaGetSymbolAddress((void**)&p_q2,   g_q2);
    cudaGetSymbolAddress((void**)&p_kv,   g_kv);
    cudaGetSymbolAddress((void**)&p_attn, g_attn);
    cudaGetSymbolAddress((void**)&p_x1,   g_x1);
    cudaGetSymbolAddress((void**)&p_x2,   g_x2);
    cudaGetSymbolAddress((void**)&p_h1,   g_h1);
    cudaGetSymbolAddress((void**)&p_eo,   g_eo);

    const float scale = 0.125f;

    // ===== Self-attention =====
    ln_kernel<<<NL, 256>>>(latents, sa_ln_g, sa_ln_b, p_lnq);
    gemm_tf32<<<dim3(24, 16), 256, GEMM_SMEM>>>(p_lnq, DD, sa_in_w, DD, p_qkv, 3 * DD,
                                                sa_in_b, nullptr, 0, DD);
    flash_tf32<<<dim3(4, BHN), 256, FA_SMEM>>>(p_qkv, 3 * DD, p_qkv + DD, 3 * DD,
                                               p_qkv + 2 * DD, 3 * DD, p_attn, LL, scale);
    gemm_tf32<<<dim3(8, 16), 256, GEMM_SMEM>>>(p_attn, DD, sa_out_w, DD, p_x1, DD,
                                               sa_out_b, latents, DD, DD);

    // ===== Cross-attention =====
    ln_kernel<<<NL, 256>>>(p_x1, ca_q_ln_g, ca_q_ln_b, p_lnq);
    ln_kernel<<<NT, 256>>>(tokens, ca_kv_ln_g, ca_kv_ln_b, p_lnt);
    gemm_tf32<<<dim3(8, 16), 256, GEMM_SMEM>>>(p_lnq, DD, ca_in_w, DD, p_q2, DD,
                                               ca_in_b, nullptr, 0, DD);
    gemm_tf32<<<dim3(16, 64), 256, GEMM_SMEM>>>(p_lnt, DD, ca_in_w + (size_t)DD * DD, DD,
                                                p_kv, 2 * DD, ca_in_b + DD, nullptr, 0, DD);
    flash_tf32<<<dim3(4, BHN), 256, FA_SMEM>>>(p_q2, DD, p_kv, 2 * DD,
                                               p_kv + DD, 2 * DD, p_attn, TT, scale);
    gemm_tf32<<<dim3(8, 16), 256, GEMM_SMEM>>>(p_attn, DD, ca_out_w, DD, p_x2, DD,
                                               ca_out_b, p_x1, DD, DD);

    // ===== MoE =====
    ln_kernel<<<NL, 256>>>(p_x2, moe_ln_g, moe_ln_b, p_lnq);
    moe_zero<<<1, 32>>>();
    router_topk<<<NL / 8, 256>>>(p_lnq, router_w, router_b);
    moe_offsets<<<1, 1>>>();
    moe_assign<<<NL / 256, 256>>>();
    moe_gemm_tf32<<<dim3(DFFN / 128, 16, EE), 256, GEMM_SMEM>>>(p_lnq, DD, 1, e_fc1_w, e_fc1_b,
                                                                DFFN, DD, p_h1, DFFN, 1);
    moe_gemm_tf32<<<dim3(DD / 128, 16, EE), 256, GEMM_SMEM>>>(p_h1, DFFN, 0, e_fc2_w, e_fc2_b,
                                                              DD, DFFN, p_eo, DD, 0);
    moe_mix<<<(NL * DD) / 256, 256>>>(p_x2, out);
}

// round 7
// speedup vs baseline: 1.1605x; 1.0699x over previous
#include <cuda_runtime.h>
#include <math.h>
#include <stdint.h>

#define DD   1024
#define HH   16
#define DHH  64
#define BB   4
#define LL   512
#define TT   2048
#define EE   8
#define KKE  2
#define DFFN 4096
#define NL   (BB*LL)
#define NT   (BB*TT)
#define BHN  (BB*HH)
#define LN_EPS 1e-5f

// ---------------- scratch ----------------
__device__ float g_lnq[(size_t)NL*DD];
__device__ float g_lnr[(size_t)NL*DD];     // unrounded LN out for router
__device__ float g_lnt[(size_t)NT*DD];
__device__ float g_qkv[(size_t)NL*3*DD];
__device__ float g_q2 [(size_t)NL*DD];
__device__ float g_kv [(size_t)NT*2*DD];
__device__ float g_attn[(size_t)NL*DD];
__device__ float g_x1 [(size_t)NL*DD];
__device__ float g_x2 [(size_t)NL*DD];
__device__ float g_h1 [(size_t)NL*KKE*DFFN];
__device__ float g_eo [(size_t)NL*KKE*DD];
__device__ int   g_idx [NL*KKE];
__device__ float g_gate[NL*KKE];
__device__ int   g_cnt[EE];
__device__ int   g_off[EE];
__device__ int   g_cur[EE];
__device__ int   g_rowlist[NL*KKE];
__device__ int   g_pairslot[NL*KKE];

// ---------------- helpers ----------------
__device__ __forceinline__ float blk_sum(float v) {
    __shared__ float sh[32];
    int lane = threadIdx.x & 31, w = threadIdx.x >> 5;
    #pragma unroll
    for (int o = 16; o; o >>= 1) v += __shfl_xor_sync(0xffffffffu, v, o);
    if (lane == 0) sh[w] = v;
    __syncthreads();
    if (w == 0) {
        float x = (lane < (int)(blockDim.x >> 5)) ? sh[lane] : 0.f;
        #pragma unroll
        for (int o = 16; o; o >>= 1) x += __shfl_xor_sync(0xffffffffu, x, o);
        if (lane == 0) sh[0] = x;
    }
    __syncthreads();
    float r = sh[0];
    __syncthreads();
    return r;
}

__device__ __forceinline__ float gelu_exact(float x) {
    return 0.5f * x * (1.f + erff(x * 0.70710678118654752f));
}

// ---------------- tf32 mma primitives ----------------
__device__ __forceinline__ uint32_t f2tf(float f) {
    uint32_t u;
    asm("cvt.rna.tf32.f32 %0, %1;" : "=r"(u) : "f"(f));
    return u;
}
__device__ __forceinline__ float rnd_tf(float f) { return __uint_as_float(f2tf(f)); }

__device__ __forceinline__ void mma8(float* cr, const uint32_t* a, const uint32_t* b) {
    asm volatile(
        "mma.sync.aligned.m16n8k8.row.col.f32.tf32.tf32.f32 "
        "{%0,%1,%2,%3}, {%4,%5,%6,%7}, {%8,%9}, {%0,%1,%2,%3};"
        : "+f"(cr[0]), "+f"(cr[1]), "+f"(cr[2]), "+f"(cr[3])
        : "r"(a[0]), "r"(a[1]), "r"(a[2]), "r"(a[3]), "r"(b[0]), "r"(b[1]));
}

__device__ __forceinline__ void ldsm4(uint32_t* r, uint32_t addr) {
    asm volatile("ldmatrix.sync.aligned.m8n8.x4.shared.b16 {%0,%1,%2,%3}, [%4];"
        : "=r"(r[0]), "=r"(r[1]), "=r"(r[2]), "=r"(r[3]) : "r"(addr));
}

__device__ __forceinline__ void cp16(uint32_t dst, const void* src) {
    asm volatile("cp.async.cg.shared.global [%0], [%1], 16;" :: "r"(dst), "l"(src));
}
__device__ __forceinline__ void cp16p(uint32_t dst, const void* src, bool valid) {
    int sz = valid ? 16 : 0;
    asm volatile("cp.async.cg.shared.global [%0], [%1], 16, %2;" :: "r"(dst), "l"(src), "r"(sz));
}
__device__ __forceinline__ void cpcommit() { asm volatile("cp.async.commit_group;"); }
__device__ __forceinline__ void cpwait1() { asm volatile("cp.async.wait_group 1;"); }
__device__ __forceinline__ void cpwait0() { asm volatile("cp.async.wait_group 0;"); }

#define TILE_AB (128*36)
#define GEMM_SMEM (4*TILE_AB*4)   /* 73728 B */

// one 32-k slab via ldmatrix. A values pre-rounded tf32 (raw), B cvt'd inline.
// a_base/b_base: per-lane smem byte addrs into the active buffer (kk=0, tile 0).
__device__ __forceinline__ void mma_slab(uint32_t a_base, uint32_t b_base,
                                         float (&acc)[4][4][4]) {
    #pragma unroll
    for (int kk = 0; kk < 4; kk++) {
        uint32_t af[4][4];
        #pragma unroll
        for (int mi = 0; mi < 4; mi++)
            ldsm4(af[mi], a_base + (mi * 16 * 36 + kk * 8) * 4);
        uint32_t bq[2][4];
        #pragma unroll
        for (int np = 0; np < 2; np++)
            ldsm4(bq[np], b_base + (np * 16 * 36 + kk * 8) * 4);
        #pragma unroll
        for (int np = 0; np < 2; np++)
            #pragma unroll
            for (int q = 0; q < 4; q++)
                bq[np][q] = f2tf(__uint_as_float(bq[np][q]));
        #pragma unroll
        for (int mi = 0; mi < 4; mi++) {
            #pragma unroll
            for (int np = 0; np < 2; np++) {
                mma8(acc[mi][np * 2 + 0], af[mi], &bq[np][0]);
                mma8(acc[mi][np * 2 + 1], af[mi], &bq[np][2]);
            }
        }
    }
}

// float-smem slab for flash attention (cvt inline; data pre-rounded -> identity).
template<int WM, int WN, bool BKN, int AST2, int BST>
__device__ __forceinline__ void mma_tile(const float* __restrict__ Ab,
                                         const float* __restrict__ Bb,
                                         int wm, int wn, int g, int c,
                                         float (&acc)[WM][WN][4]) {
    #pragma unroll
    for (int kk = 0; kk < 4; kk++) {
        const int k0 = kk * 8;
        uint32_t af[WM][4];
        #pragma unroll
        for (int mi = 0; mi < WM; mi++) {
            const float* Ar = Ab + (wm + mi * 16 + g) * AST2 + k0 + c;
            af[mi][0] = f2tf(Ar[0]);
            af[mi][1] = f2tf(Ar[8 * AST2]);
            af[mi][2] = f2tf(Ar[4]);
            af[mi][3] = f2tf(Ar[8 * AST2 + 4]);
        }
        uint32_t bf[WN][2];
        #pragma unroll
        for (int ni = 0; ni < WN; ni++) {
            if (BKN) {
                const float* Br = Bb + (k0 + c) * BST + wn + ni * 8 + g;
                bf[ni][0] = f2tf(Br[0]);
                bf[ni][1] = f2tf(Br[4 * BST]);
            } else {
                const float* Br = Bb + (wn + ni * 8 + g) * BST + k0 + c;
                bf[ni][0] = f2tf(Br[0]);
                bf[ni][1] = f2tf(Br[4]);
            }
        }
        #pragma unroll
        for (int mi = 0; mi < WM; mi++)
            #pragma unroll
            for (int ni = 0; ni < WN; ni++)
                mma8(acc[mi][ni], af[mi], bf[ni]);
    }
}

// ---------------- layernorm (writes tf32-rounded; optional raw copy) ----------------
__global__ void __launch_bounds__(256) ln_kernel(const float* __restrict__ x,
                                                 const float* __restrict__ g,
                                                 const float* __restrict__ b,
                                                 float* __restrict__ y,
                                                 float* __restrict__ yraw) {
    size_t row = blockIdx.x;
    const float* xr = x + row * DD;
    float* yr = y + row * DD;
    int t = threadIdx.x;
    float v[4];
    float s = 0.f;
    #pragma unroll
    for (int i = 0; i < 4; i++) { v[i] = xr[t + 256 * i]; s += v[i]; }
    s = blk_sum(s);
    float mean = s * (1.f / DD);
    float s2 = 0.f;
    #pragma unroll
    for (int i = 0; i < 4; i++) { float d = v[i] - mean; s2 += d * d; }
    s2 = blk_sum(s2);
    float inv = rsqrtf(s2 * (1.f / DD) + LN_EPS);
    #pragma unroll
    for (int i = 0; i < 4; i++) {
        int cc = t + 256 * i;
        float o = (v[i] - mean) * inv * g[cc] + b[cc];
        yr[cc] = rnd_tf(o);
        if (yraw) yraw[row * DD + cc] = o;
    }
}

// ---------------- tf32 GEMM: 128x128, cp.async + ldmatrix ----------------
__global__ void __launch_bounds__(256, 2) gemm_tf32(const float* __restrict__ A, int lda,
                                                    const float* __restrict__ W, int ldw,
                                                    float* __restrict__ C, int ldc,
                                                    const float* __restrict__ bias,
                                                    const float* __restrict__ resid, int ldr,
                                                    int Kd, int round_out) {
    extern __shared__ float sm[];
    float* As = sm;
    float* Bs = sm + 2 * TILE_AB;
    int t = threadIdx.x;
    int row0 = blockIdx.y * 128, col0 = blockIdx.x * 128;
    int lrow = t >> 1, lcol = (t & 1) * 16;
    const float* Ag = A + (size_t)(row0 + lrow) * lda + lcol;
    const float* Wg = W + (size_t)(col0 + lrow) * ldw + lcol;
    uint32_t as_u = (uint32_t)__cvta_generic_to_shared(As);
    uint32_t bs_u = (uint32_t)__cvta_generic_to_shared(Bs);
    uint32_t as0 = as_u + (lrow * 36 + lcol) * 4;
    uint32_t bs0 = bs_u + (lrow * 36 + lcol) * 4;
    int warp = t >> 5, lane = t & 31, g = lane >> 2, c = lane & 3;
    int wm = (warp >> 2) * 64, wn = (warp & 3) * 32;
    // ldmatrix per-lane bases
    uint32_t a_frag = as_u + ((wm + (lane & 15)) * 36 + (lane >> 4) * 4) * 4;
    uint32_t b_frag = bs_u + ((wn + ((lane >> 4) << 3) + (lane & 7)) * 36 + ((lane >> 3) & 1) * 4) * 4;
    float acc[4][4][4] = {};
    int KT = Kd >> 5;
    #pragma unroll
    for (int i = 0; i < 4; i++) cp16(as0 + i * 16, Ag + i * 4);
    #pragma unroll
    for (int i = 0; i < 4; i++) cp16(bs0 + i * 16, Wg + i * 4);
    cpcommit();
    for (int kt = 0; kt < KT; kt++) {
        int cb = kt & 1;
        if (kt + 1 < KT) {
            int nb = (kt + 1) & 1;
            const float* a = Ag + (kt + 1) * 32;
            const float* w = Wg + (kt + 1) * 32;
            #pragma unroll
            for (int i = 0; i < 4; i++) cp16(as0 + nb * TILE_AB * 4 + i * 16, a + i * 4);
            #pragma unroll
            for (int i = 0; i < 4; i++) cp16(bs0 + nb * TILE_AB * 4 + i * 16, w + i * 4);
            cpcommit();
            cpwait1();
        } else cpwait0();
        __syncthreads();
        mma_slab(a_frag + cb * TILE_AB * 4, b_frag + cb * TILE_AB * 4, acc);
        __syncthreads();
    }
    #pragma unroll
    for (int mi = 0; mi < 4; mi++) {
        int r = row0 + wm + mi * 16 + g;
        #pragma unroll
        for (int ni = 0; ni < 4; ni++) {
            int cc = col0 + wn + ni * 8 + c * 2;
            float v0 = acc[mi][ni][0], v1 = acc[mi][ni][1];
            float v2 = acc[mi][ni][2], v3 = acc[mi][ni][3];
            if (bias) { float b0 = bias[cc], b1 = bias[cc + 1]; v0 += b0; v1 += b1; v2 += b0; v3 += b1; }
            if (resid) {
                const float* q0 = resid + (size_t)r * ldr + cc;
                const float* q1 = resid + (size_t)(r + 8) * ldr + cc;
                v0 += q0[0]; v1 += q0[1]; v2 += q1[0]; v3 += q1[1];
            }
            if (round_out) { v0 = rnd_tf(v0); v1 = rnd_tf(v1); v2 = rnd_tf(v2); v3 = rnd_tf(v3); }
            *(float2*)(C + (size_t)r * ldc + cc) = make_float2(v0, v1);
            *(float2*)(C + (size_t)(r + 8) * ldc + cc) = make_float2(v2, v3);
        }
    }
}

// ---------------- fused flash attention (tf32) ----------------
#define FA_N 64
#define FA_QS (128*68)
#define FA_KV (64*68)
#define FA_SMEM ((FA_QS + 4*FA_KV + FA_QS)*4)

__global__ void __launch_bounds__(256) flash_tf32(const float* __restrict__ Q, int ldq,
                                                  const float* __restrict__ Kp, int ldk,
                                                  const float* __restrict__ Vp, int ldv,
                                                  float* __restrict__ O, int Lk, float scale) {
    extern __shared__ float sm[];
    float* Qs = sm;
    float* Ks = Qs + FA_QS;
    float* Vs = Ks + 2 * FA_KV;
    float* Ps = Vs + 2 * FA_KV;
    int bh = blockIdx.y, b = bh >> 4, h = bh & 15;
    int q0 = blockIdx.x * 128;
    int t = threadIdx.x;
    const float* Qg = Q + ((size_t)(b * LL + q0)) * ldq + h * DHH;
    const float* Kg = Kp + ((size_t)b * Lk) * ldk + h * DHH;
    const float* Vg = Vp + ((size_t)b * Lk) * ldv + h * DHH;
    uint32_t qs0 = (uint32_t)__cvta_generic_to_shared(Qs);
    uint32_t ks0 = (uint32_t)__cvta_generic_to_shared(Ks);
    uint32_t vs0 = (uint32_t)__cvta_generic_to_shared(Vs);
    {
        int row = t >> 1, segb = (t & 1) * 8;
        const float* qr = Qg + (size_t)row * ldq;
        #pragma unroll
        for (int j = 0; j < 8; j++)
            cp16(qs0 + (row * 68 + (segb + j) * 4) * 4, qr + (segb + j) * 4);
    }
    int kr = t >> 2, kcb = (t & 3) * 16;
    {
        const float* kg = Kg + (size_t)kr * ldk + kcb;
        const float* vg = Vg + (size_t)kr * ldv + kcb;
        uint32_t kb = ks0 + (kr * 68 + kcb) * 4;
        uint32_t vb = vs0 + (kr * 68 + kcb) * 4;
        #pragma unroll
        for (int j = 0; j < 4; j++) cp16(kb + j * 16, kg + j * 4);
        #pragma unroll
        for (int j = 0; j < 4; j++) cp16(vb + j * 16, vg + j * 4);
    }
    cpcommit();
    int warp = t >> 5, lane = t & 31, g = lane >> 2, c = lane & 3;
    int wr = warp * 16;
    float Oa[1][8][4] = {};
    float m0 = -INFINITY, m1 = -INFINITY, l0 = 0.f, l1 = 0.f;
    int niter = Lk / FA_N;
    for (int it = 0; it < niter; it++) {
        if (it + 1 < niter) {
            int buf = (it + 1) & 1;
            const float* kg = Kg + (size_t)((it + 1) * FA_N + kr) * ldk + kcb;
            const float* vg = Vg + (size_t)((it + 1) * FA_N + kr) * ldv + kcb;
            uint32_t kb = ks0 + (buf * FA_KV + kr * 68 + kcb) * 4;
            uint32_t vb = vs0 + (buf * FA_KV + kr * 68 + kcb) * 4;
            #pragma unroll
            for (int j = 0; j < 4; j++) cp16(kb + j * 16, kg + j * 4);
            #pragma unroll
            for (int j = 0; j < 4; j++) cp16(vb + j * 16, vg + j * 4);
            cpcommit();
            cpwait1();
        } else cpwait0();
        __syncthreads();
        const float* Kb = Ks + (it & 1) * FA_KV;
        const float* Vb = Vs + (it & 1) * FA_KV;
        float S[1][8][4] = {};
        mma_tile<1, 8, false, 68, 68>(Qs, Kb, wr, 0, g, c, S);
        mma_tile<1, 8, false, 68, 68>(Qs + 32, Kb + 32, wr, 0, g, c, S);
        float rm0 = -INFINITY, rm1 = -INFINITY;
        #pragma unroll
        for (int ni = 0; ni < 8; ni++) {
            #pragma unroll
            for (int j = 0; j < 4; j++) S[0][ni][j] *= scale;
            rm0 = fmaxf(rm0, fmaxf(S[0][ni][0], S[0][ni][1]));
            rm1 = fmaxf(rm1, fmaxf(S[0][ni][2], S[0][ni][3]));
        }
        rm0 = fmaxf(rm0, __shfl_xor_sync(0xffffffffu, rm0, 1));
        rm0 = fmaxf(rm0, __shfl_xor_sync(0xffffffffu, rm0, 2));
        rm1 = fmaxf(rm1, __shfl_xor_sync(0xffffffffu, rm1, 1));
        rm1 = fmaxf(rm1, __shfl_xor_sync(0xffffffffu, rm1, 2));
        float mn0 = fmaxf(m0, rm0), mn1 = fmaxf(m1, rm1);
        float a0 = __expf(m0 - mn0), a1 = __expf(m1 - mn1);
        float ps0 = 0.f, ps1 = 0.f;
        #pragma unroll
        for (int ni = 0; ni < 8; ni++) {
            float p0 = __expf(S[0][ni][0] - mn0);
            float p1 = __expf(S[0][ni][1] - mn0);
            float p2 = __expf(S[0][ni][2] - mn1);
            float p3 = __expf(S[0][ni][3] - mn1);
            ps0 += p0 + p1; ps1 += p2 + p3;
            *(float2*)&Ps[(wr + g) * 68 + ni * 8 + 2 * c] = make_float2(p0, p1);
            *(float2*)&Ps[(wr + g + 8) * 68 + ni * 8 + 2 * c] = make_float2(p2, p3);
        }
        ps0 += __shfl_xor_sync(0xffffffffu, ps0, 1);
        ps0 += __shfl_xor_sync(0xffffffffu, ps0, 2);
        ps1 += __shfl_xor_sync(0xffffffffu, ps1, 1);
        ps1 += __shfl_xor_sync(0xffffffffu, ps1, 2);
        l0 = l0 * a0 + ps0;
        l1 = l1 * a1 + ps1;
        m0 = mn0; m1 = mn1;
        #pragma unroll
        for (int ni = 0; ni < 8; ni++) {
            Oa[0][ni][0] *= a0; Oa[0][ni][1] *= a0;
            Oa[0][ni][2] *= a1; Oa[0][ni][3] *= a1;
        }
        __syncwarp();
        mma_tile<1, 8, true, 68, 68>(Ps, Vb, wr, 0, g, c, Oa);
        mma_tile<1, 8, true, 68, 68>(Ps + 32, Vb + 32 * 68, wr, 0, g, c, Oa);
        __syncthreads();
    }
    float i0 = 1.f / l0, i1 = 1.f / l1;
    float* Og = O + ((size_t)(b * LL + q0 + wr)) * DD + h * DHH;
    #pragma unroll
    for (int ni = 0; ni < 8; ni++) {
        int cc = ni * 8 + 2 * c;
        *(float2*)(Og + (size_t)g * DD + cc) =
            make_float2(rnd_tf(Oa[0][ni][0] * i0), rnd_tf(Oa[0][ni][1] * i0));
        *(float2*)(Og + (size_t)(g + 8) * DD + cc) =
            make_float2(rnd_tf(Oa[0][ni][2] * i1), rnd_tf(Oa[0][ni][3] * i1));
    }
}

// ---------------- MoE routing ----------------
__global__ void moe_zero() {
    if (threadIdx.x < EE) g_cnt[threadIdx.x] = 0;
}

__global__ void __launch_bounds__(256) router_topk(const float* __restrict__ H,
                                                   const float* __restrict__ rw,
                                                   const float* __restrict__ rb) {
    int warp = (blockIdx.x * blockDim.x + threadIdx.x) >> 5;
    int lane = threadIdx.x & 31;
    if (warp >= NL) return;
    const float* h = H + (size_t)warp * DD;
    float logit[EE];
    #pragma unroll
    for (int e = 0; e < EE; e++) {
        const float* w = rw + (size_t)e * DD;
        float s = 0.f;
        for (int d = lane; d < DD; d += 32) s += h[d] * w[d];
        #pragma unroll
        for (int o = 16; o; o >>= 1) s += __shfl_xor_sync(0xffffffffu, s, o);
        logit[e] = s + rb[e];
    }
    if (lane == 0) {
        int i0 = 0; float m0 = logit[0];
        #pragma unroll
        for (int e = 1; e < EE; e++) if (logit[e] > m0) { m0 = logit[e]; i0 = e; }
        int i1 = -1; float m1 = -INFINITY;
        #pragma unroll
        for (int e = 0; e < EE; e++) if (e != i0 && logit[e] > m1) { m1 = logit[e]; i1 = e; }
        float z = expf(m1 - m0);
        float inv = 1.f / (1.f + z);
        g_idx[warp * 2] = i0;  g_idx[warp * 2 + 1] = i1;
        g_gate[warp * 2] = inv; g_gate[warp * 2 + 1] = z * inv;
        atomicAdd(&g_cnt[i0], 1);
        atomicAdd(&g_cnt[i1], 1);
    }
}

__global__ void moe_offsets() {
    if (threadIdx.x == 0) {
        int s = 0;
        for (int e = 0; e < EE; e++) { g_off[e] = s; s += g_cnt[e]; g_cur[e] = 0; }
    }
}

__global__ void __launch_bounds__(256) moe_assign() {
    int n = blockIdx.x * blockDim.x + threadIdx.x;
    if (n >= NL) return;
    #pragma unroll
    for (int k = 0; k < KKE; k++) {
        int e = g_idx[n * 2 + k];
        int pos = atomicAdd(&g_cur[e], 1);
        int slot = g_off[e] + pos;
        g_rowlist[slot] = n;
        g_pairslot[n * 2 + k] = slot;
    }
}

// ---------------- MoE grouped tf32 GEMM (128x128, cp.async + ldmatrix) ----------------
__global__ void __launch_bounds__(256, 2) moe_gemm_tf32(const float* __restrict__ A, int lda, int gather,
                                                        const float* __restrict__ W,
                                                        const float* __restrict__ bias,
                                                        int M, int Kd,
                                                        float* __restrict__ C, int ldc, int act) {
    extern __shared__ float sm[];
    float* As = sm;
    float* Bs = sm + 2 * TILE_AB;
    int e = blockIdx.z;
    int count = g_cnt[e];
    int row0 = blockIdx.y * 128;
    if (row0 >= count) return;
    int base = g_off[e];
    const float* We = W + (size_t)e * M * Kd;
    const float* be = bias + (size_t)e * M;
    int col0 = blockIdx.x * 128;
    int t = threadIdx.x;
    int lrow = t >> 1, lcol = (t & 1) * 16;
    int arow = row0 + lrow;
    bool valid = arow < count;
    int src;
    if (gather) src = g_rowlist[base + (valid ? arow : 0)];
    else        src = base + (valid ? arow : 0);
    const float* Ag = A + (size_t)src * lda + lcol;
    const float* Wg = We + (size_t)(col0 + lrow) * Kd + lcol;
    uint32_t as_u = (uint32_t)__cvta_generic_to_shared(As);
    uint32_t bs_u = (uint32_t)__cvta_generic_to_shared(Bs);
    uint32_t as0 = as_u + (lrow * 36 + lcol) * 4;
    uint32_t bs0 = bs_u + (lrow * 36 + lcol) * 4;
    int warp = t >> 5, lane = t & 31, g = lane >> 2, c = lane & 3;
    int wm = (warp >> 2) * 64, wn = (warp & 3) * 32;
    uint32_t a_frag = as_u + ((wm + (lane & 15)) * 36 + (lane >> 4) * 4) * 4;
    uint32_t b_frag = bs_u + ((wn + ((lane >> 4) << 3) + (lane & 7)) * 36 + ((lane >> 3) & 1) * 4) * 4;
    float acc[4][4][4] = {};
    int KT = Kd >> 5;
    #pragma unroll
    for (int i = 0; i < 4; i++) cp16p(as0 + i * 16, Ag + i * 4, valid);
    #pragma unroll
    for (int i = 0; i < 4; i++) cp16(bs0 + i * 16, Wg + i * 4);
    cpcommit();
    for (int kt = 0; kt < KT; kt++) {
        int cb = kt & 1;
        if (kt + 1 < KT) {
            int nb = (kt + 1) & 1;
            const float* a = Ag + (kt + 1) * 32;
            const float* w = Wg + (kt + 1) * 32;
            #pragma unroll
            for (int i = 0; i < 4; i++) cp16p(as0 + nb * TILE_AB * 4 + i * 16, a + i * 4, valid);
            #pragma unroll
            for (int i = 0; i < 4; i++) cp16(bs0 + nb * TILE_AB * 4 + i * 16, w + i * 4);
            cpcommit();
            cpwait1();
        } else cpwait0();
        __syncthreads();
        mma_slab(a_frag + cb * TILE_AB * 4, b_frag + cb * TILE_AB * 4, acc);
        __syncthreads();
    }
    #pragma unroll
    for (int mi = 0; mi < 4; mi++) {
        int r = row0 + wm + mi * 16 + g;
        #pragma unroll
        for (int ni = 0; ni < 4; ni++) {
            int cc = col0 + wn + ni * 8 + c * 2;
            float b0 = be[cc], b1 = be[cc + 1];
            if (r < count) {
                float v0 = acc[mi][ni][0] + b0, v1 = acc[mi][ni][1] + b1;
                if (act) { v0 = rnd_tf(gelu_exact(v0)); v1 = rnd_tf(gelu_exact(v1)); }
                *(float2*)(C + (size_t)(base + r) * ldc + cc) = make_float2(v0, v1);
            }
            if (r + 8 < count) {
                float v2 = acc[mi][ni][2] + b0, v3 = acc[mi][ni][3] + b1;
                if (act) { v2 = rnd_tf(gelu_exact(v2)); v3 = rnd_tf(gelu_exact(v3)); }
                *(float2*)(C + (size_t)(base + r + 8) * ldc + cc) = make_float2(v2, v3);
            }
        }
    }
}

// ---------------- final mix ----------------
__global__ void __launch_bounds__(256) moe_mix(const float* __restrict__ x2,
                                               float* __restrict__ out) {
    int i = blockIdx.x * 256 + threadIdx.x;
    int n = i >> 10;
    int d = i & 1023;
    float v = x2[i];
    int s0 = g_pairslot[n * 2], s1 = g_pairslot[n * 2 + 1];
    v += g_gate[n * 2]     * g_eo[(size_t)s0 * DD + d];
    v += g_gate[n * 2 + 1] * g_eo[(size_t)s1 * DD + d];
    out[i] = v;
}

// ---------------- launch ----------------
extern "C" void kernel_launch(void* const* d_in, const int* in_sizes, int n_in,
                              void* d_out, int out_size) {
    const float* latents    = (const float*)d_in[0];
    const float* tokens     = (const float*)d_in[1];
    const float* sa_ln_g    = (const float*)d_in[2];
    const float* sa_ln_b    = (const float*)d_in[3];
    const float* sa_in_w    = (const float*)d_in[4];
    const float* sa_in_b    = (const float*)d_in[5];
    const float* sa_out_w   = (const float*)d_in[6];
    const float* sa_out_b   = (const float*)d_in[7];
    const float* ca_q_ln_g  = (const float*)d_in[8];
    const float* ca_q_ln_b  = (const float*)d_in[9];
    const float* ca_kv_ln_g = (const float*)d_in[10];
    const float* ca_kv_ln_b = (const float*)d_in[11];
    const float* ca_in_w    = (const float*)d_in[12];
    const float* ca_in_b    = (const float*)d_in[13];
    const float* ca_out_w   = (const float*)d_in[14];
    const float* ca_out_b   = (const float*)d_in[15];
    const float* moe_ln_g   = (const float*)d_in[16];
    const float* moe_ln_b   = (const float*)d_in[17];
    const float* router_w   = (const float*)d_in[18];
    const float* router_b   = (const float*)d_in[19];
    const float* e_fc1_w    = (const float*)d_in[20];
    const float* e_fc1_b    = (const float*)d_in[21];
    const float* e_fc2_w    = (const float*)d_in[22];
    const float* e_fc2_b    = (const float*)d_in[23];
    float* out = (float*)d_out;

    static int s_attr_done = 0;
    if (!s_attr_done) {
        cudaFuncSetAttribute(gemm_tf32, cudaFuncAttributeMaxDynamicSharedMemorySize, GEMM_SMEM);
        cudaFuncSetAttribute(moe_gemm_tf32, cudaFuncAttributeMaxDynamicSharedMemorySize, GEMM_SMEM);
        cudaFuncSetAttribute(flash_tf32, cudaFuncAttributeMaxDynamicSharedMemorySize, FA_SMEM);
        s_attr_done = 1;
    }

    float *p_lnq, *p_lnr, *p_lnt, *p_qkv, *p_q2, *p_kv, *p_attn, *p_x1, *p_x2, *p_h1, *p_eo;
    cudaGetSymbolAddress((void**)&p_lnq,  g_lnq);
    cudaGetSymbolAddress((void**)&p_lnr,  g_lnr);
    cudaGetSymbolAddress((void**)&p_lnt,  g_lnt);
    cudaGetSymbolAddress((void**)&p_qkv,  g_qkv);
    cudaGetSymbolAddress((void**)&p_q2,   g_q2);
    cudaGetSymbolAddress((void**)&p_kv,   g_kv);
    cudaGetSymbolAddress((void**)&p_attn, g_attn);
    cudaGetSymbolAddress((void**)&p_x1,   g_x1);
    cudaGetSymbolAddress((void**)&p_x2,   g_x2);
    cudaGetSymbolAddress((void**)&p_h1,   g_h1);
    cudaGetSymbolAddress((void**)&p_eo,   g_eo);

    const float scale = 0.125f;

    // ===== Self-attention =====
    ln_kernel<<<NL, 256>>>(latents, sa_ln_g, sa_ln_b, p_lnq, nullptr);
    gemm_tf32<<<dim3(24, 16), 256, GEMM_SMEM>>>(p_lnq, DD, sa_in_w, DD, p_qkv, 3 * DD,
                                                sa_in_b, nullptr, 0, DD, 1);
    flash_tf32<<<dim3(4, BHN), 256, FA_SMEM>>>(p_qkv, 3 * DD, p_qkv + DD, 3 * DD,
                                               p_qkv + 2 * DD, 3 * DD, p_attn, LL, scale);
    gemm_tf32<<<dim3(8, 16), 256, GEMM_SMEM>>>(p_attn, DD, sa_out_w, DD, p_x1, DD,
                                               sa_out_b, latents, DD, DD, 0);

    // ===== Cross-attention =====
    ln_kernel<<<NL, 256>>>(p_x1, ca_q_ln_g, ca_q_ln_b, p_lnq, nullptr);
    ln_kernel<<<NT, 256>>>(tokens, ca_kv_ln_g, ca_kv_ln_b, p_lnt, nullptr);
    gemm_tf32<<<dim3(8, 16), 256, GEMM_SMEM>>>(p_lnq, DD, ca_in_w, DD, p_q2, DD,
                                               ca_in_b, nullptr, 0, DD, 1);
    gemm_tf32<<<dim3(16, 64), 256, GEMM_SMEM>>>(p_lnt, DD, ca_in_w + (size_t)DD * DD, DD,
                                                p_kv, 2 * DD, ca_in_b + DD, nullptr, 0, DD, 1);
    flash_tf32<<<dim3(4, BHN), 256, FA_SMEM>>>(p_q2, DD, p_kv, 2 * DD,
                                               p_kv + DD, 2 * DD, p_attn, TT, scale);
    gemm_tf32<<<dim3(8, 16), 256, GEMM_SMEM>>>(p_attn, DD, ca_out_w, DD, p_x2, DD,
                                               ca_out_b, p_x1, DD, DD, 0);

    // ===== MoE =====
    ln_kernel<<<NL, 256>>>(p_x2, moe_ln_g, moe_ln_b, p_lnq, p_lnr);
    moe_zero<<<1, 32>>>();
    router_topk<<<NL / 8, 256>>>(p_lnr, router_w, router_b);
    moe_offsets<<<1, 1>>>();
    moe_assign<<<NL / 256, 256>>>();
    moe_gemm_tf32<<<dim3(DFFN / 128, 16, EE), 256, GEMM_SMEM>>>(p_lnq, DD, 1, e_fc1_w, e_fc1_b,
                                                                DFFN, DD, p_h1, DFFN, 1);
    moe_gemm_tf32<<<dim3(DD / 128, 16, EE), 256, GEMM_SMEM>>>(p_h1, DFFN, 0, e_fc2_w, e_fc2_b,
                                                              DD, DFFN, p_eo, DD, 0);
    moe_mix<<<(NL * DD) / 256, 256>>>(p_x2, out);
}

// round 8
// speedup vs baseline: 1.1964x; 1.0309x over previous
#include <cuda_runtime.h>
#include <math.h>
#include <stdint.h>

#define DD   1024
#define HH   16
#define DHH  64
#define BB   4
#define LL   512
#define TT   2048
#define EE   8
#define KKE  2
#define DFFN 4096
#define NL   (BB*LL)
#define NT   (BB*TT)
#define BHN  (BB*HH)
#define LN_EPS 1e-5f

// ---------------- scratch ----------------
__device__ float g_lnq[(size_t)NL*DD];
__device__ float g_lnr[(size_t)NL*DD];
__device__ float g_lnt[(size_t)NT*DD];
__device__ float g_qkv[(size_t)NL*3*DD];
__device__ float g_q2 [(size_t)NL*DD];
__device__ float g_kv [(size_t)NT*2*DD];
__device__ float g_attn[(size_t)NL*DD];
__device__ float g_x1 [(size_t)NL*DD];
__device__ float g_x2 [(size_t)NL*DD];
__device__ float g_h1 [(size_t)NL*KKE*DFFN];
__device__ float g_eo [(size_t)NL*KKE*DD];
__device__ int   g_idx [NL*KKE];
__device__ float g_gate[NL*KKE];
__device__ int   g_cnt[EE];
__device__ int   g_off[EE];
__device__ int   g_cur[EE];
__device__ int   g_rowlist[NL*KKE];
__device__ int   g_pairslot[NL*KKE];

// ---------------- helpers ----------------
__device__ __forceinline__ float blk_sum(float v) {
    __shared__ float sh[32];
    int lane = threadIdx.x & 31, w = threadIdx.x >> 5;
    #pragma unroll
    for (int o = 16; o; o >>= 1) v += __shfl_xor_sync(0xffffffffu, v, o);
    if (lane == 0) sh[w] = v;
    __syncthreads();
    if (w == 0) {
        float x = (lane < (int)(blockDim.x >> 5)) ? sh[lane] : 0.f;
        #pragma unroll
        for (int o = 16; o; o >>= 1) x += __shfl_xor_sync(0xffffffffu, x, o);
        if (lane == 0) sh[0] = x;
    }
    __syncthreads();
    float r = sh[0];
    __syncthreads();
    return r;
}

__device__ __forceinline__ float gelu_exact(float x) {
    return 0.5f * x * (1.f + erff(x * 0.70710678118654752f));
}

// ---------------- tf32 mma primitives ----------------
__device__ __forceinline__ uint32_t f2tf(float f) {
    uint32_t u;
    asm("cvt.rna.tf32.f32 %0, %1;" : "=r"(u) : "f"(f));
    return u;
}
__device__ __forceinline__ float rnd_tf(float f) { return __uint_as_float(f2tf(f)); }

__device__ __forceinline__ void mma8(float* cr, const uint32_t* a, const uint32_t* b) {
    asm volatile(
        "mma.sync.aligned.m16n8k8.row.col.f32.tf32.tf32.f32 "
        "{%0,%1,%2,%3}, {%4,%5,%6,%7}, {%8,%9}, {%0,%1,%2,%3};"
        : "+f"(cr[0]), "+f"(cr[1]), "+f"(cr[2]), "+f"(cr[3])
        : "r"(a[0]), "r"(a[1]), "r"(a[2]), "r"(a[3]), "r"(b[0]), "r"(b[1]));
}

__device__ __forceinline__ void ldsm4(uint32_t* r, uint32_t addr) {
    asm volatile("ldmatrix.sync.aligned.m8n8.x4.shared.b16 {%0,%1,%2,%3}, [%4];"
        : "=r"(r[0]), "=r"(r[1]), "=r"(r[2]), "=r"(r[3]) : "r"(addr));
}

__device__ __forceinline__ void cp16(uint32_t dst, const void* src) {
    asm volatile("cp.async.cg.shared.global [%0], [%1], 16;" :: "r"(dst), "l"(src));
}
__device__ __forceinline__ void cp16p(uint32_t dst, const void* src, bool valid) {
    int sz = valid ? 16 : 0;
    asm volatile("cp.async.cg.shared.global [%0], [%1], 16, %2;" :: "r"(dst), "l"(src), "r"(sz));
}
__device__ __forceinline__ void cpcommit() { asm volatile("cp.async.commit_group;"); }
__device__ __forceinline__ void cpwait1() { asm volatile("cp.async.wait_group 1;"); }
__device__ __forceinline__ void cpwait0() { asm volatile("cp.async.wait_group 0;"); }

// 3-stage ring: per stage [A 128x36 | B 128x36]
#define TILE_AB (128*36)
#define STAGE_F (2*TILE_AB)                 /* floats per stage */
#define NST 3
#define GEMM_SMEM (NST*STAGE_F*4)           /* 110592 B */

// one 32-k slab via ldmatrix. A pre-rounded tf32 (raw), B cvt'd inline.
__device__ __forceinline__ void mma_slab(uint32_t a_base, uint32_t b_base,
                                         float (&acc)[4][4][4]) {
    #pragma unroll
    for (int kk = 0; kk < 4; kk++) {
        uint32_t af[4][4];
        #pragma unroll
        for (int mi = 0; mi < 4; mi++)
            ldsm4(af[mi], a_base + (mi * 16 * 36 + kk * 8) * 4);
        uint32_t bq[2][4];
        #pragma unroll
        for (int np = 0; np < 2; np++)
            ldsm4(bq[np], b_base + (np * 16 * 36 + kk * 8) * 4);
        #pragma unroll
        for (int np = 0; np < 2; np++)
            #pragma unroll
            for (int q = 0; q < 4; q++)
                bq[np][q] = f2tf(__uint_as_float(bq[np][q]));
        #pragma unroll
        for (int mi = 0; mi < 4; mi++) {
            #pragma unroll
            for (int np = 0; np < 2; np++) {
                mma8(acc[mi][np * 2 + 0], af[mi], &bq[np][0]);
                mma8(acc[mi][np * 2 + 1], af[mi], &bq[np][2]);
            }
        }
    }
}

// float-smem slab for flash attention (cvt inline).
template<int WM, int WN, bool BKN, int AST2, int BST>
__device__ __forceinline__ void mma_tile(const float* __restrict__ Ab,
                                         const float* __restrict__ Bb,
                                         int wm, int wn, int g, int c,
                                         float (&acc)[WM][WN][4]) {
    #pragma unroll
    for (int kk = 0; kk < 4; kk++) {
        const int k0 = kk * 8;
        uint32_t af[WM][4];
        #pragma unroll
        for (int mi = 0; mi < WM; mi++) {
            const float* Ar = Ab + (wm + mi * 16 + g) * AST2 + k0 + c;
            af[mi][0] = f2tf(Ar[0]);
            af[mi][1] = f2tf(Ar[8 * AST2]);
            af[mi][2] = f2tf(Ar[4]);
            af[mi][3] = f2tf(Ar[8 * AST2 + 4]);
        }
        uint32_t bf[WN][2];
        #pragma unroll
        for (int ni = 0; ni < WN; ni++) {
            if (BKN) {
                const float* Br = Bb + (k0 + c) * BST + wn + ni * 8 + g;
                bf[ni][0] = f2tf(Br[0]);
                bf[ni][1] = f2tf(Br[4 * BST]);
            } else {
                const float* Br = Bb + (wn + ni * 8 + g) * BST + k0 + c;
                bf[ni][0] = f2tf(Br[0]);
                bf[ni][1] = f2tf(Br[4]);
            }
        }
        #pragma unroll
        for (int mi = 0; mi < WM; mi++)
            #pragma unroll
            for (int ni = 0; ni < WN; ni++)
                mma8(acc[mi][ni], af[mi], bf[ni]);
    }
}

// ---------------- layernorm ----------------
__global__ void __launch_bounds__(256) ln_kernel(const float* __restrict__ x,
                                                 const float* __restrict__ g,
                                                 const float* __restrict__ b,
                                                 float* __restrict__ y,
                                                 float* __restrict__ yraw) {
    size_t row = blockIdx.x;
    const float* xr = x + row * DD;
    float* yr = y + row * DD;
    int t = threadIdx.x;
    float v[4];
    float s = 0.f;
    #pragma unroll
    for (int i = 0; i < 4; i++) { v[i] = xr[t + 256 * i]; s += v[i]; }
    s = blk_sum(s);
    float mean = s * (1.f / DD);
    float s2 = 0.f;
    #pragma unroll
    for (int i = 0; i < 4; i++) { float d = v[i] - mean; s2 += d * d; }
    s2 = blk_sum(s2);
    float inv = rsqrtf(s2 * (1.f / DD) + LN_EPS);
    #pragma unroll
    for (int i = 0; i < 4; i++) {
        int cc = t + 256 * i;
        float o = (v[i] - mean) * inv * g[cc] + b[cc];
        yr[cc] = rnd_tf(o);
        if (yraw) yraw[row * DD + cc] = o;
    }
}

// ---------------- tf32 GEMM: 128x128, 3-stage cp.async + ldmatrix ----------------
__global__ void __launch_bounds__(256, 2) gemm_tf32(const float* __restrict__ A, int lda,
                                                    const float* __restrict__ W, int ldw,
                                                    float* __restrict__ C, int ldc,
                                                    const float* __restrict__ bias,
                                                    const float* __restrict__ resid, int ldr,
                                                    int Kd, int round_out) {
    extern __shared__ float sm[];
    int t = threadIdx.x;
    int row0 = blockIdx.y * 128, col0 = blockIdx.x * 128;
    int lrow = t >> 1, lcol = (t & 1) * 16;
    const float* Ag = A + (size_t)(row0 + lrow) * lda + lcol;
    const float* Wg = W + (size_t)(col0 + lrow) * ldw + lcol;
    uint32_t sm_u = (uint32_t)__cvta_generic_to_shared(sm);
    uint32_t as0 = sm_u + (lrow * 36 + lcol) * 4;                // A in stage
    uint32_t bs0 = sm_u + (TILE_AB + lrow * 36 + lcol) * 4;      // B in stage
    int warp = t >> 5, lane = t & 31, g = lane >> 2, c = lane & 3;
    int wm = (warp >> 2) * 64, wn = (warp & 3) * 32;
    uint32_t a_frag = sm_u + ((wm + (lane & 15)) * 36 + (lane >> 4) * 4) * 4;
    uint32_t b_frag = sm_u + (TILE_AB + (wn + ((lane >> 4) << 3) + (lane & 7)) * 36 + ((lane >> 3) & 1) * 4) * 4;
    float acc[4][4][4] = {};
    int KT = Kd >> 5;
    // prologue: stages 0,1
    #pragma unroll
    for (int s = 0; s < 2; s++) {
        const float* a = Ag + s * 32;
        const float* w = Wg + s * 32;
        uint32_t so = (uint32_t)(s * STAGE_F * 4);
        #pragma unroll
        for (int i = 0; i < 4; i++) cp16(as0 + so + i * 16, a + i * 4);
        #pragma unroll
        for (int i = 0; i < 4; i++) cp16(bs0 + so + i * 16, w + i * 4);
        cpcommit();
    }
    int sl = 0;  // stage of current slab
    for (int kt = 0; kt < KT; kt++) {
        cpwait1();
        __syncthreads();
        if (kt + 2 < KT) {
            int sn = sl + 2; if (sn >= NST) sn -= NST;
            const float* a = Ag + (kt + 2) * 32;
            const float* w = Wg + (kt + 2) * 32;
            uint32_t so = (uint32_t)(sn * STAGE_F * 4);
            #pragma unroll
            for (int i = 0; i < 4; i++) cp16(as0 + so + i * 16, a + i * 4);
            #pragma unroll
            for (int i = 0; i < 4; i++) cp16(bs0 + so + i * 16, w + i * 4);
            cpcommit();
        }
        uint32_t so = (uint32_t)(sl * STAGE_F * 4);
        mma_slab(a_frag + so, b_frag + so, acc);
        if (++sl == NST) sl = 0;
    }
    #pragma unroll
    for (int mi = 0; mi < 4; mi++) {
        int r = row0 + wm + mi * 16 + g;
        #pragma unroll
        for (int ni = 0; ni < 4; ni++) {
            int cc = col0 + wn + ni * 8 + c * 2;
            float v0 = acc[mi][ni][0], v1 = acc[mi][ni][1];
            float v2 = acc[mi][ni][2], v3 = acc[mi][ni][3];
            if (bias) { float b0 = bias[cc], b1 = bias[cc + 1]; v0 += b0; v1 += b1; v2 += b0; v3 += b1; }
            if (resid) {
                const float* q0 = resid + (size_t)r * ldr + cc;
                const float* q1 = resid + (size_t)(r + 8) * ldr + cc;
                v0 += q0[0]; v1 += q0[1]; v2 += q1[0]; v3 += q1[1];
            }
            if (round_out) { v0 = rnd_tf(v0); v1 = rnd_tf(v1); v2 = rnd_tf(v2); v3 = rnd_tf(v3); }
            *(float2*)(C + (size_t)r * ldc + cc) = make_float2(v0, v1);
            *(float2*)(C + (size_t)(r + 8) * ldc + cc) = make_float2(v2, v3);
        }
    }
}

// ---------------- fused flash attention (tf32, unchanged) ----------------
#define FA_N 64
#define FA_QS (128*68)
#define FA_KV (64*68)
#define FA_SMEM ((FA_QS + 4*FA_KV + FA_QS)*4)

__global__ void __launch_bounds__(256) flash_tf32(const float* __restrict__ Q, int ldq,
                                                  const float* __restrict__ Kp, int ldk,
                                                  const float* __restrict__ Vp, int ldv,
                                                  float* __restrict__ O, int Lk, float scale) {
    extern __shared__ float sm[];
    float* Qs = sm;
    float* Ks = Qs + FA_QS;
    float* Vs = Ks + 2 * FA_KV;
    float* Ps = Vs + 2 * FA_KV;
    int bh = blockIdx.y, b = bh >> 4, h = bh & 15;
    int q0 = blockIdx.x * 128;
    int t = threadIdx.x;
    const float* Qg = Q + ((size_t)(b * LL + q0)) * ldq + h * DHH;
    const float* Kg = Kp + ((size_t)b * Lk) * ldk + h * DHH;
    const float* Vg = Vp + ((size_t)b * Lk) * ldv + h * DHH;
    uint32_t qs0 = (uint32_t)__cvta_generic_to_shared(Qs);
    uint32_t ks0 = (uint32_t)__cvta_generic_to_shared(Ks);
    uint32_t vs0 = (uint32_t)__cvta_generic_to_shared(Vs);
    {
        int row = t >> 1, segb = (t & 1) * 8;
        const float* qr = Qg + (size_t)row * ldq;
        #pragma unroll
        for (int j = 0; j < 8; j++)
            cp16(qs0 + (row * 68 + (segb + j) * 4) * 4, qr + (segb + j) * 4);
    }
    int kr = t >> 2, kcb = (t & 3) * 16;
    {
        const float* kg = Kg + (size_t)kr * ldk + kcb;
        const float* vg = Vg + (size_t)kr * ldv + kcb;
        uint32_t kb = ks0 + (kr * 68 + kcb) * 4;
        uint32_t vb = vs0 + (kr * 68 + kcb) * 4;
        #pragma unroll
        for (int j = 0; j < 4; j++) cp16(kb + j * 16, kg + j * 4);
        #pragma unroll
        for (int j = 0; j < 4; j++) cp16(vb + j * 16, vg + j * 4);
    }
    cpcommit();
    int warp = t >> 5, lane = t & 31, g = lane >> 2, c = lane & 3;
    int wr = warp * 16;
    float Oa[1][8][4] = {};
    float m0 = -INFINITY, m1 = -INFINITY, l0 = 0.f, l1 = 0.f;
    int niter = Lk / FA_N;
    for (int it = 0; it < niter; it++) {
        if (it + 1 < niter) {
            int buf = (it + 1) & 1;
            const float* kg = Kg + (size_t)((it + 1) * FA_N + kr) * ldk + kcb;
            const float* vg = Vg + (size_t)((it + 1) * FA_N + kr) * ldv + kcb;
            uint32_t kb = ks0 + (buf * FA_KV + kr * 68 + kcb) * 4;
            uint32_t vb = vs0 + (buf * FA_KV + kr * 68 + kcb) * 4;
            #pragma unroll
            for (int j = 0; j < 4; j++) cp16(kb + j * 16, kg + j * 4);
            #pragma unroll
            for (int j = 0; j < 4; j++) cp16(vb + j * 16, vg + j * 4);
            cpcommit();
            cpwait1();
        } else cpwait0();
        __syncthreads();
        const float* Kb = Ks + (it & 1) * FA_KV;
        const float* Vb = Vs + (it & 1) * FA_KV;
        float S[1][8][4] = {};
        mma_tile<1, 8, false, 68, 68>(Qs, Kb, wr, 0, g, c, S);
        mma_tile<1, 8, false, 68, 68>(Qs + 32, Kb + 32, wr, 0, g, c, S);
        float rm0 = -INFINITY, rm1 = -INFINITY;
        #pragma unroll
        for (int ni = 0; ni < 8; ni++) {
            #pragma unroll
            for (int j = 0; j < 4; j++) S[0][ni][j] *= scale;
            rm0 = fmaxf(rm0, fmaxf(S[0][ni][0], S[0][ni][1]));
            rm1 = fmaxf(rm1, fmaxf(S[0][ni][2], S[0][ni][3]));
        }
        rm0 = fmaxf(rm0, __shfl_xor_sync(0xffffffffu, rm0, 1));
        rm0 = fmaxf(rm0, __shfl_xor_sync(0xffffffffu, rm0, 2));
        rm1 = fmaxf(rm1, __shfl_xor_sync(0xffffffffu, rm1, 1));
        rm1 = fmaxf(rm1, __shfl_xor_sync(0xffffffffu, rm1, 2));
        float mn0 = fmaxf(m0, rm0), mn1 = fmaxf(m1, rm1);
        float a0 = __expf(m0 - mn0), a1 = __expf(m1 - mn1);
        float ps0 = 0.f, ps1 = 0.f;
        #pragma unroll
        for (int ni = 0; ni < 8; ni++) {
            float p0 = __expf(S[0][ni][0] - mn0);
            float p1 = __expf(S[0][ni][1] - mn0);
            float p2 = __expf(S[0][ni][2] - mn1);
            float p3 = __expf(S[0][ni][3] - mn1);
            ps0 += p0 + p1; ps1 += p2 + p3;
            *(float2*)&Ps[(wr + g) * 68 + ni * 8 + 2 * c] = make_float2(p0, p1);
            *(float2*)&Ps[(wr + g + 8) * 68 + ni * 8 + 2 * c] = make_float2(p2, p3);
        }
        ps0 += __shfl_xor_sync(0xffffffffu, ps0, 1);
        ps0 += __shfl_xor_sync(0xffffffffu, ps0, 2);
        ps1 += __shfl_xor_sync(0xffffffffu, ps1, 1);
        ps1 += __shfl_xor_sync(0xffffffffu, ps1, 2);
        l0 = l0 * a0 + ps0;
        l1 = l1 * a1 + ps1;
        m0 = mn0; m1 = mn1;
        #pragma unroll
        for (int ni = 0; ni < 8; ni++) {
            Oa[0][ni][0] *= a0; Oa[0][ni][1] *= a0;
            Oa[0][ni][2] *= a1; Oa[0][ni][3] *= a1;
        }
        __syncwarp();
        mma_tile<1, 8, true, 68, 68>(Ps, Vb, wr, 0, g, c, Oa);
        mma_tile<1, 8, true, 68, 68>(Ps + 32, Vb + 32 * 68, wr, 0, g, c, Oa);
        __syncthreads();
    }
    float i0 = 1.f / l0, i1 = 1.f / l1;
    float* Og = O + ((size_t)(b * LL + q0 + wr)) * DD + h * DHH;
    #pragma unroll
    for (int ni = 0; ni < 8; ni++) {
        int cc = ni * 8 + 2 * c;
        *(float2*)(Og + (size_t)g * DD + cc) =
            make_float2(rnd_tf(Oa[0][ni][0] * i0), rnd_tf(Oa[0][ni][1] * i0));
        *(float2*)(Og + (size_t)(g + 8) * DD + cc) =
            make_float2(rnd_tf(Oa[0][ni][2] * i1), rnd_tf(Oa[0][ni][3] * i1));
    }
}

// ---------------- MoE routing ----------------
__global__ void moe_zero() {
    if (threadIdx.x < EE) g_cnt[threadIdx.x] = 0;
}

__global__ void __launch_bounds__(256) router_topk(const float* __restrict__ H,
                                                   const float* __restrict__ rw,
                                                   const float* __restrict__ rb) {
    int warp = (blockIdx.x * blockDim.x + threadIdx.x) >> 5;
    int lane = threadIdx.x & 31;
    if (warp >= NL) return;
    const float* h = H + (size_t)warp * DD;
    float logit[EE];
    #pragma unroll
    for (int e = 0; e < EE; e++) {
        const float* w = rw + (size_t)e * DD;
        float s = 0.f;
        for (int d = lane; d < DD; d += 32) s += h[d] * w[d];
        #pragma unroll
        for (int o = 16; o; o >>= 1) s += __shfl_xor_sync(0xffffffffu, s, o);
        logit[e] = s + rb[e];
    }
    if (lane == 0) {
        int i0 = 0; float m0 = logit[0];
        #pragma unroll
        for (int e = 1; e < EE; e++) if (logit[e] > m0) { m0 = logit[e]; i0 = e; }
        int i1 = -1; float m1 = -INFINITY;
        #pragma unroll
        for (int e = 0; e < EE; e++) if (e != i0 && logit[e] > m1) { m1 = logit[e]; i1 = e; }
        float z = expf(m1 - m0);
        float inv = 1.f / (1.f + z);
        g_idx[warp * 2] = i0;  g_idx[warp * 2 + 1] = i1;
        g_gate[warp * 2] = inv; g_gate[warp * 2 + 1] = z * inv;
        atomicAdd(&g_cnt[i0], 1);
        atomicAdd(&g_cnt[i1], 1);
    }
}

__global__ void moe_offsets() {
    if (threadIdx.x == 0) {
        int s = 0;
        for (int e = 0; e < EE; e++) { g_off[e] = s; s += g_cnt[e]; g_cur[e] = 0; }
    }
}

__global__ void __launch_bounds__(256) moe_assign() {
    int n = blockIdx.x * blockDim.x + threadIdx.x;
    if (n >= NL) return;
    #pragma unroll
    for (int k = 0; k < KKE; k++) {
        int e = g_idx[n * 2 + k];
        int pos = atomicAdd(&g_cur[e], 1);
        int slot = g_off[e] + pos;
        g_rowlist[slot] = n;
        g_pairslot[n * 2 + k] = slot;
    }
}

// ---------------- MoE grouped tf32 GEMM (3-stage pipeline) ----------------
__global__ void __launch_bounds__(256, 2) moe_gemm_tf32(const float* __restrict__ A, int lda, int gather,
                                                        const float* __restrict__ W,
                                                        const float* __restrict__ bias,
                                                        int M, int Kd,
                                                        float* __restrict__ C, int ldc, int act) {
    extern __shared__ float sm[];
    int e = blockIdx.z;
    int count = g_cnt[e];
    int row0 = blockIdx.y * 128;
    if (row0 >= count) return;
    int base = g_off[e];
    const float* We = W + (size_t)e * M * Kd;
    const float* be = bias + (size_t)e * M;
    int col0 = blockIdx.x * 128;
    int t = threadIdx.x;
    int lrow = t >> 1, lcol = (t & 1) * 16;
    int arow = row0 + lrow;
    bool valid = arow < count;
    int src;
    if (gather) src = g_rowlist[base + (valid ? arow : 0)];
    else        src = base + (valid ? arow : 0);
    const float* Ag = A + (size_t)src * lda + lcol;
    const float* Wg = We + (size_t)(col0 + lrow) * Kd + lcol;
    uint32_t sm_u = (uint32_t)__cvta_generic_to_shared(sm);
    uint32_t as0 = sm_u + (lrow * 36 + lcol) * 4;
    uint32_t bs0 = sm_u + (TILE_AB + lrow * 36 + lcol) * 4;
    int warp = t >> 5, lane = t & 31, g = lane >> 2, c = lane & 3;
    int wm = (warp >> 2) * 64, wn = (warp & 3) * 32;
    uint32_t a_frag = sm_u + ((wm + (lane & 15)) * 36 + (lane >> 4) * 4) * 4;
    uint32_t b_frag = sm_u + (TILE_AB + (wn + ((lane >> 4) << 3) + (lane & 7)) * 36 + ((lane >> 3) & 1) * 4) * 4;
    float acc[4][4][4] = {};
    int KT = Kd >> 5;
    #pragma unroll
    for (int s = 0; s < 2; s++) {
        const float* a = Ag + s * 32;
        const float* w = Wg + s * 32;
        uint32_t so = (uint32_t)(s * STAGE_F * 4);
        #pragma unroll
        for (int i = 0; i < 4; i++) cp16p(as0 + so + i * 16, a + i * 4, valid);
        #pragma unroll
        for (int i = 0; i < 4; i++) cp16(bs0 + so + i * 16, w + i * 4);
        cpcommit();
    }
    int sl = 0;
    for (int kt = 0; kt < KT; kt++) {
        cpwait1();
        __syncthreads();
        if (kt + 2 < KT) {
            int sn = sl + 2; if (sn >= NST) sn -= NST;
            const float* a = Ag + (kt + 2) * 32;
            const float* w = Wg + (kt + 2) * 32;
            uint32_t so = (uint32_t)(sn * STAGE_F * 4);
            #pragma unroll
            for (int i = 0; i < 4; i++) cp16p(as0 + so + i * 16, a + i * 4, valid);
            #pragma unroll
            for (int i = 0; i < 4; i++) cp16(bs0 + so + i * 16, w + i * 4);
            cpcommit();
        }
        uint32_t so = (uint32_t)(sl * STAGE_F * 4);
        mma_slab(a_frag + so, b_frag + so, acc);
        if (++sl == NST) sl = 0;
    }
    #pragma unroll
    for (int mi = 0; mi < 4; mi++) {
        int r = row0 + wm + mi * 16 + g;
        #pragma unroll
        for (int ni = 0; ni < 4; ni++) {
            int cc = col0 + wn + ni * 8 + c * 2;
            float b0 = be[cc], b1 = be[cc + 1];
            if (r < count) {
                float v0 = acc[mi][ni][0] + b0, v1 = acc[mi][ni][1] + b1;
                if (act) { v0 = rnd_tf(gelu_exact(v0)); v1 = rnd_tf(gelu_exact(v1)); }
                *(float2*)(C + (size_t)(base + r) * ldc + cc) = make_float2(v0, v1);
            }
            if (r + 8 < count) {
                float v2 = acc[mi][ni][2] + b0, v3 = acc[mi][ni][3] + b1;
                if (act) { v2 = rnd_tf(gelu_exact(v2)); v3 = rnd_tf(gelu_exact(v3)); }
                *(float2*)(C + (size_t)(base + r + 8) * ldc + cc) = make_float2(v2, v3);
            }
        }
    }
}

// ---------------- final mix ----------------
__global__ void __launch_bounds__(256) moe_mix(const float* __restrict__ x2,
                                               float* __restrict__ out) {
    int i = blockIdx.x * 256 + threadIdx.x;
    int n = i >> 10;
    int d = i & 1023;
    float v = x2[i];
    int s0 = g_pairslot[n * 2], s1 = g_pairslot[n * 2 + 1];
    v += g_gate[n * 2]     * g_eo[(size_t)s0 * DD + d];
    v += g_gate[n * 2 + 1] * g_eo[(size_t)s1 * DD + d];
    out[i] = v;
}

// ---------------- launch ----------------
extern "C" void kernel_launch(void* const* d_in, const int* in_sizes, int n_in,
                              void* d_out, int out_size) {
    const float* latents    = (const float*)d_in[0];
    const float* tokens     = (const float*)d_in[1];
    const float* sa_ln_g    = (const float*)d_in[2];
    const float* sa_ln_b    = (const float*)d_in[3];
    const float* sa_in_w    = (const float*)d_in[4];
    const float* sa_in_b    = (const float*)d_in[5];
    const float* sa_out_w   = (const float*)d_in[6];
    const float* sa_out_b   = (const float*)d_in[7];
    const float* ca_q_ln_g  = (const float*)d_in[8];
    const float* ca_q_ln_b  = (const float*)d_in[9];
    const float* ca_kv_ln_g = (const float*)d_in[10];
    const float* ca_kv_ln_b = (const float*)d_in[11];
    const float* ca_in_w    = (const float*)d_in[12];
    const float* ca_in_b    = (const float*)d_in[13];
    const float* ca_out_w   = (const float*)d_in[14];
    const float* ca_out_b   = (const float*)d_in[15];
    const float* moe_ln_g   = (const float*)d_in[16];
    const float* moe_ln_b   = (const float*)d_in[17];
    const float* router_w   = (const float*)d_in[18];
    const float* router_b   = (const float*)d_in[19];
    const float* e_fc1_w    = (const float*)d_in[20];
    const float* e_fc1_b    = (const float*)d_in[21];
    const float* e_fc2_w    = (const float*)d_in[22];
    const float* e_fc2_b    = (const float*)d_in[23];
    float* out = (float*)d_out;

    static int s_attr_done = 0;
    if (!s_attr_done) {
        cudaFuncSetAttribute(gemm_tf32, cudaFuncAttributeMaxDynamicSharedMemorySize, GEMM_SMEM);
        cudaFuncSetAttribute(moe_gemm_tf32, cudaFuncAttributeMaxDynamicSharedMemorySize, GEMM_SMEM);
        cudaFuncSetAttribute(flash_tf32, cudaFuncAttributeMaxDynamicSharedMemorySize, FA_SMEM);
        s_attr_done = 1;
    }

    float *p_lnq, *p_lnr, *p_lnt, *p_qkv, *p_q2, *p_kv, *p_attn, *p_x1, *p_x2, *p_h1, *p_eo;
    cudaGetSymbolAddress((void**)&p_lnq,  g_lnq);
    cudaGetSymbolAddress((void**)&p_lnr,  g_lnr);
    cudaGetSymbolAddress((void**)&p_lnt,  g_lnt);
    cudaGetSymbolAddress((void**)&p_qkv,  g_qkv);
    cudaGetSymbolAddress((void**)&p_q2,   g_q2);
    cudaGetSymbolAddress((void**)&p_kv,   g_kv);
    cudaGetSymbolAddress((void**)&p_attn, g_attn);
    cudaGetSymbolAddress((void**)&p_x1,   g_x1);
    cudaGetSymbolAddress((void**)&p_x2,   g_x2);
    cudaGetSymbolAddress((void**)&p_h1,   g_h1);
    cudaGetSymbolAddress((void**)&p_eo,   g_eo);

    const float scale = 0.125f;

    // ===== Self-attention =====
    ln_kernel<<<NL, 256>>>(latents, sa_ln_g, sa_ln_b, p_lnq, nullptr);
    gemm_tf32<<<dim3(24, 16), 256, GEMM_SMEM>>>(p_lnq, DD, sa_in_w, DD, p_qkv, 3 * DD,
                                                sa_in_b, nullptr, 0, DD, 1);
    flash_tf32<<<dim3(4, BHN), 256, FA_SMEM>>>(p_qkv, 3 * DD, p_qkv + DD, 3 * DD,
                                               p_qkv + 2 * DD, 3 * DD, p_attn, LL, scale);
    gemm_tf32<<<dim3(8, 16), 256, GEMM_SMEM>>>(p_attn, DD, sa_out_w, DD, p_x1, DD,
                                               sa_out_b, latents, DD, DD, 0);

    // ===== Cross-attention =====
    ln_kernel<<<NL, 256>>>(p_x1, ca_q_ln_g, ca_q_ln_b, p_lnq, nullptr);
    ln_kernel<<<NT, 256>>>(tokens, ca_kv_ln_g, ca_kv_ln_b, p_lnt, nullptr);
    gemm_tf32<<<dim3(8, 16), 256, GEMM_SMEM>>>(p_lnq, DD, ca_in_w, DD, p_q2, DD,
                                               ca_in_b, nullptr, 0, DD, 1);
    gemm_tf32<<<dim3(16, 64), 256, GEMM_SMEM>>>(p_lnt, DD, ca_in_w + (size_t)DD * DD, DD,
                                                p_kv, 2 * DD, ca_in_b + DD, nullptr, 0, DD, 1);
    flash_tf32<<<dim3(4, BHN), 256, FA_SMEM>>>(p_q2, DD, p_kv, 2 * DD,
                                               p_kv + DD, 2 * DD, p_attn, TT, scale);
    gemm_tf32<<<dim3(8, 16), 256, GEMM_SMEM>>>(p_attn, DD, ca_out_w, DD, p_x2, DD,
                                               ca_out_b, p_x1, DD, DD, 0);

    // ===== MoE =====
    ln_kernel<<<NL, 256>>>(p_x2, moe_ln_g, moe_ln_b, p_lnq, p_lnr);
    moe_zero<<<1, 32>>>();
    router_topk<<<NL / 8, 256>>>(p_lnr, router_w, router_b);
    moe_offsets<<<1, 1>>>();
    moe_assign<<<NL / 256, 256>>>();
    moe_gemm_tf32<<<dim3(DFFN / 128, 16, EE), 256, GEMM_SMEM>>>(p_lnq, DD, 1, e_fc1_w, e_fc1_b,
                                                                DFFN, DD, p_h1, DFFN, 1);
    moe_gemm_tf32<<<dim3(DD / 128, 16, EE), 256, GEMM_SMEM>>>(p_h1, DFFN, 0, e_fc2_w, e_fc2_b,
                                                              DD, DFFN, p_eo, DD, 0);
    moe_mix<<<(NL * DD) / 256, 256>>>(p_x2, out);
}